// round 1
// baseline (speedup 1.0000x reference)
#include <cuda_runtime.h>
#include <math.h>

#define N_ATOMS 50000
#define N_EDGES 800000
#define TBL 8192
#define DMAXF 14.0f
#define LN2F 0.6931471805599453f

// ---------------- device scratch (static, no runtime allocation) ----------------
__device__ float g_h   [N_ATOMS * 128];
__device__ float g_hf  [N_ATOMS * 128];
__device__ float g_agg [N_ATOMS * 128];
__device__ float g_t1  [N_ATOMS * 128];
__device__ float g_d   [N_EDGES];
__device__ float g_sd  [N_EDGES];
__device__ int   g_ssrc[N_EDGES];
__device__ int   g_counts[N_ATOMS];
__device__ int   g_start [N_ATOMS];
__device__ int   g_cursor[N_ATOMS];
__device__ float g_table[3 * TBL * 128];

__device__ __forceinline__ float sspf(float x) {
    // jax.nn.softplus(x) - ln2 == max(x,0) + log1p(exp(-|x|)) - ln2
    return fmaxf(x, 0.0f) + log1pf(expf(-fabsf(x))) - LN2F;
}

// ---------------- init: h = embed[r], zero counts, zero out ----------------
__global__ void k_init(const int* __restrict__ r, const float* __restrict__ embed,
                       float* __restrict__ out, int out_size) {
    int idx = blockIdx.x * blockDim.x + threadIdx.x;
    if (idx < N_ATOMS * 32) {
        int atom = idx >> 5, j = idx & 31;
        ((float4*)g_h)[atom * 32 + j] = ((const float4*)embed)[(size_t)r[atom] * 32 + j];
    }
    if (idx < N_ATOMS) g_counts[idx] = 0;
    if (idx < out_size) out[idx] = 0.0f;
}

// ---------------- edges: distances + dst histogram ----------------
__global__ void k_edges(const int* __restrict__ a, const float* __restrict__ xyz) {
    int e = blockIdx.x * blockDim.x + threadIdx.x;
    if (e >= N_EDGES) return;
    int d0 = a[2 * e], s0 = a[2 * e + 1];
    float dx = xyz[3 * d0 + 0] - xyz[3 * s0 + 0];
    float dy = xyz[3 * d0 + 1] - xyz[3 * s0 + 1];
    float dz = xyz[3 * d0 + 2] - xyz[3 * s0 + 2];
    g_d[e] = sqrtf(dx * dx + dy * dy + dz * dz + 1e-12f);
    atomicAdd(&g_counts[d0], 1);
}

// ---------------- single-block exclusive scan over 50000 counters ----------------
__global__ __launch_bounds__(1024) void k_scan() {
    __shared__ int sh[1024];
    __shared__ int carry;
    int t = threadIdx.x;
    if (t == 0) carry = 0;
    for (int base = 0; base < N_ATOMS; base += 1024) {
        int i = base + t;
        int v = (i < N_ATOMS) ? g_counts[i] : 0;
        sh[t] = v;
        __syncthreads();
        #pragma unroll
        for (int off = 1; off < 1024; off <<= 1) {
            int x = (t >= off) ? sh[t - off] : 0;
            __syncthreads();
            sh[t] += x;
            __syncthreads();
        }
        int excl = carry + sh[t] - v;
        if (i < N_ATOMS) { g_start[i] = excl; g_cursor[i] = excl; }
        __syncthreads();
        if (t == 0) carry += sh[1023];
        __syncthreads();
    }
}

// ---------------- scatter edges into dst-sorted order ----------------
__global__ void k_scatter(const int* __restrict__ a) {
    int e = blockIdx.x * blockDim.x + threadIdx.x;
    if (e >= N_EDGES) return;
    int d0 = a[2 * e];
    int pos = atomicAdd(&g_cursor[d0], 1);
    g_ssrc[pos] = a[2 * e + 1];
    g_sd[pos] = g_d[e];
}

// ---------------- build W(d) tables: 3 layers x TBL entries x 128 ----------------
__global__ __launch_bounds__(128) void k_table(const float* __restrict__ fw1,
                                               const float* __restrict__ fb1,
                                               const float* __restrict__ fw2,
                                               const float* __restrict__ fb2) {
    int L = blockIdx.x / TBL, e = blockIdx.x % TBL;
    int j = threadIdx.x;
    __shared__ float gs[32];
    __shared__ float ts[128];
    float d = (float)e * (DMAXF / (float)(TBL - 1));
    if (j < 32) {
        float width = 5.0f / 31.0f;
        float off = (float)j * width;
        float x = d - off;
        gs[j] = expf((-0.5f / (width * width)) * x * x);
    }
    __syncthreads();
    const float* w1 = fw1 + (size_t)L * 32 * 128;
    float t = fb1[L * 128 + j];
    #pragma unroll
    for (int k = 0; k < 32; k++) t = fmaf(gs[k], w1[k * 128 + j], t);
    ts[j] = sspf(t);
    __syncthreads();
    const float* w2 = fw2 + (size_t)L * 128 * 128;
    float w = fb2[L * 128 + j];
    #pragma unroll 8
    for (int k = 0; k < 128; k++) w = fmaf(ts[k], w2[k * 128 + j], w);
    g_table[((size_t)L * TBL + e) * 128 + j] = w;
}

// ---------------- aggregation: one warp per atom, float4 lanes ----------------
__global__ __launch_bounds__(128) void k_agg(const float* __restrict__ tbl) {
    int atom = blockIdx.x * 4 + threadIdx.y;
    int j = threadIdx.x;               // 0..31 -> float4 over 128 features
    int s = g_start[atom], c = g_counts[atom];
    float4 acc = make_float4(0.f, 0.f, 0.f, 0.f);
    const float4* hf4 = (const float4*)g_hf;
    const float4* t4 = (const float4*)tbl;
    for (int e = 0; e < c; e++) {
        int src = __ldg(&g_ssrc[s + e]);
        float d = __ldg(&g_sd[s + e]);
        float u = fminf(d * ((float)(TBL - 1) / DMAXF), (float)(TBL - 1) - 1e-3f);
        int i0 = (int)u;
        float f = u - (float)i0;
        float4 w0 = t4[i0 * 32 + j];
        float4 w1 = t4[i0 * 32 + 32 + j];
        float4 hv = hf4[(size_t)src * 32 + j];
        acc.x += hv.x * fmaf(f, w1.x - w0.x, w0.x);
        acc.y += hv.y * fmaf(f, w1.y - w0.y, w0.y);
        acc.z += hv.z * fmaf(f, w1.z - w0.z, w0.z);
        acc.w += hv.w * fmaf(f, w1.w - w0.w, w0.w);
    }
    ((float4*)g_agg)[atom * 32 + j] = acc;
}

// ---------------- register-tiled SGEMM: C[M,128] = act(A[M,128]@W[128,128]+b) (+C) ----------------
template <int ACT, int RES>
__global__ __launch_bounds__(256) void k_gemm128(const float* __restrict__ A,
                                                 const float* __restrict__ W,
                                                 const float* __restrict__ bias,
                                                 float* __restrict__ C, int M) {
    __shared__ float As[16][128];   // transposed A tile
    __shared__ float Ws[16][128];
    int tid = threadIdx.x;
    int row0 = blockIdx.x * 128;
    int tx = tid & 15, ty = tid >> 4;
    float acc[8][8];
    #pragma unroll
    for (int i = 0; i < 8; i++)
        #pragma unroll
        for (int jj = 0; jj < 8; jj++) acc[i][jj] = 0.0f;

    for (int kt = 0; kt < 128; kt += 16) {
        #pragma unroll
        for (int i = 0; i < 2; i++) {
            int id = tid + i * 256;           // 0..511
            int rr = id >> 2;                 // 0..127
            int kc = (id & 3) * 4;
            float4 v = make_float4(0.f, 0.f, 0.f, 0.f);
            if (row0 + rr < M) v = *(const float4*)(A + (size_t)(row0 + rr) * 128 + kt + kc);
            As[kc + 0][rr] = v.x; As[kc + 1][rr] = v.y;
            As[kc + 2][rr] = v.z; As[kc + 3][rr] = v.w;
        }
        #pragma unroll
        for (int i = 0; i < 2; i++) {
            int id = tid + i * 256;
            int wr = id >> 5;                 // 0..15
            int wc = (id & 31) * 4;
            *(float4*)&Ws[wr][wc] = *(const float4*)(W + (size_t)(kt + wr) * 128 + wc);
        }
        __syncthreads();
        #pragma unroll
        for (int k = 0; k < 16; k++) {
            float av[8], bv[8];
            *(float4*)&av[0] = *(const float4*)&As[k][ty * 8];
            *(float4*)&av[4] = *(const float4*)&As[k][ty * 8 + 4];
            *(float4*)&bv[0] = *(const float4*)&Ws[k][tx * 8];
            *(float4*)&bv[4] = *(const float4*)&Ws[k][tx * 8 + 4];
            #pragma unroll
            for (int i = 0; i < 8; i++)
                #pragma unroll
                for (int jj = 0; jj < 8; jj++) acc[i][jj] = fmaf(av[i], bv[jj], acc[i][jj]);
        }
        __syncthreads();
    }

    float4 b0 = *(const float4*)&bias[tx * 8];
    float4 b1 = *(const float4*)&bias[tx * 8 + 4];
    #pragma unroll
    for (int i = 0; i < 8; i++) {
        int grow = row0 + ty * 8 + i;
        if (grow >= M) continue;
        float4 v0, v1;
        v0.x = acc[i][0] + b0.x; v0.y = acc[i][1] + b0.y;
        v0.z = acc[i][2] + b0.z; v0.w = acc[i][3] + b0.w;
        v1.x = acc[i][4] + b1.x; v1.y = acc[i][5] + b1.y;
        v1.z = acc[i][6] + b1.z; v1.w = acc[i][7] + b1.w;
        if (ACT) {
            v0.x = sspf(v0.x); v0.y = sspf(v0.y); v0.z = sspf(v0.z); v0.w = sspf(v0.w);
            v1.x = sspf(v1.x); v1.y = sspf(v1.y); v1.z = sspf(v1.z); v1.w = sspf(v1.w);
        }
        float* cp = C + (size_t)grow * 128 + tx * 8;
        if (RES) {
            float4 r0 = *(const float4*)cp;
            float4 r1 = *(const float4*)(cp + 4);
            v0.x += r0.x; v0.y += r0.y; v0.z += r0.z; v0.w += r0.w;
            v1.x += r1.x; v1.y += r1.y; v1.z += r1.z; v1.w += r1.w;
        }
        *(float4*)cp = v0;
        *(float4*)(cp + 4) = v1;
    }
}

// ---------------- readout: y = ssp(h@aw1+ab1)@aw2+ab2, block-sum into out ----------------
__global__ __launch_bounds__(256) void k_readout(const float* __restrict__ h,
                                                 const float* __restrict__ aw1,
                                                 const float* __restrict__ ab1,
                                                 const float* __restrict__ aw2,
                                                 const float* __restrict__ ab2,
                                                 float* __restrict__ out,
                                                 const int* __restrict__ nper) {
    __shared__ float w1s[128 * 64];   // 32 KB
    __shared__ float hs[4][128];
    __shared__ float red[4][2];
    int tid = threadIdx.x;
    int np = nper ? nper[0] : 5000;
    for (int i = tid; i < 128 * 64; i += 256) w1s[i] = aw1[i];
    int j = tid & 63;
    int al = tid >> 6;                 // 0..3
    float w2 = aw2[j];
    float b1 = ab1[j];
    int atom0 = blockIdx.x * 32;
    for (int round = 0; round < 8; round++) {
        __syncthreads();
        for (int i = tid; i < 512; i += 256) {
            int aa = i >> 7, kk = i & 127;
            int ga = atom0 + round * 4 + aa;
            hs[aa][kk] = (ga < N_ATOMS) ? h[(size_t)ga * 128 + kk] : 0.0f;
        }
        __syncthreads();
        float t = b1;
        #pragma unroll 16
        for (int k = 0; k < 128; k++) t = fmaf(hs[al][k], w1s[k * 64 + j], t);
        t = sspf(t) * w2;
        #pragma unroll
        for (int off = 16; off; off >>= 1) t += __shfl_down_sync(0xffffffffu, t, off);
        if ((tid & 31) == 0) red[al][j >> 5] = t;
        __syncthreads();
        int atom = atom0 + round * 4 + al;
        if (j == 0 && atom < N_ATOMS) {
            float y = red[al][0] + red[al][1] + ab2[0];
            atomicAdd(&out[atom / np], y);
        }
    }
}

// ---------------- host ----------------
extern "C" void kernel_launch(void* const* d_in, const int* in_sizes, int n_in,
                              void* d_out, int out_size) {
    const int*   r   = (const int*)d_in[0];
    const float* xyz = (const float*)d_in[1];
    const int*   a   = (const int*)d_in[2];
    int base = 3;
    const int* nper = nullptr;
    if (n_in >= 19) { nper = (const int*)d_in[3]; base = 4; }
    const float* embed = (const float*)d_in[base + 0];
    const float* fw1   = (const float*)d_in[base + 1];
    const float* fb1   = (const float*)d_in[base + 2];
    const float* fw2   = (const float*)d_in[base + 3];
    const float* fb2   = (const float*)d_in[base + 4];
    const float* afw   = (const float*)d_in[base + 5];
    const float* afb   = (const float*)d_in[base + 6];
    const float* ow1   = (const float*)d_in[base + 7];
    const float* ob1   = (const float*)d_in[base + 8];
    const float* ow2   = (const float*)d_in[base + 9];
    const float* ob2   = (const float*)d_in[base + 10];
    const float* aw1   = (const float*)d_in[base + 11];
    const float* ab1   = (const float*)d_in[base + 12];
    const float* aw2   = (const float*)d_in[base + 13];
    const float* ab2   = (const float*)d_in[base + 14];
    float* out = (float*)d_out;

    float *ph, *phf, *pagg, *pt1, *ptbl;
    cudaGetSymbolAddress((void**)&ph,   g_h);
    cudaGetSymbolAddress((void**)&phf,  g_hf);
    cudaGetSymbolAddress((void**)&pagg, g_agg);
    cudaGetSymbolAddress((void**)&pt1,  g_t1);
    cudaGetSymbolAddress((void**)&ptbl, g_table);

    k_init<<<(N_ATOMS * 32 + 255) / 256, 256>>>(r, embed, out, out_size);
    k_edges<<<(N_EDGES + 255) / 256, 256>>>(a, xyz);
    k_scan<<<1, 1024>>>();
    k_scatter<<<(N_EDGES + 255) / 256, 256>>>(a);
    k_table<<<3 * TBL, 128>>>(fw1, fb1, fw2, fb2);

    int gemm_grid = (N_ATOMS + 127) / 128;
    for (int L = 0; L < 3; L++) {
        k_gemm128<0, 0><<<gemm_grid, 256>>>(ph, afw + (size_t)L * 16384, afb + L * 128, phf, N_ATOMS);
        k_agg<<<N_ATOMS / 4, dim3(32, 4)>>>(ptbl + (size_t)L * TBL * 128);
        k_gemm128<1, 0><<<gemm_grid, 256>>>(pagg, ow1 + (size_t)L * 16384, ob1 + L * 128, pt1, N_ATOMS);
        k_gemm128<0, 1><<<gemm_grid, 256>>>(pt1, ow2 + (size_t)L * 16384, ob2 + L * 128, ph, N_ATOMS);
    }
    k_readout<<<(N_ATOMS + 31) / 32, 256>>>(ph, aw1, ab1, aw2, ab2, out, nper);
}

// round 2
// speedup vs baseline: 1.0081x; 1.0081x over previous
#include <cuda_runtime.h>
#include <cuda_fp16.h>
#include <math.h>

#define N_ATOMS 50000
#define N_EDGES 800000
#define TBL 8192
#define DMAXF 14.0f
#define LN2F 0.6931471805599453f
#define KC 16

// ---------------- device scratch ----------------
__device__ float  g_h   [N_ATOMS * 128];
__device__ __half g_hf  [N_ATOMS * 128];
__device__ float  g_agg [N_ATOMS * 128];
__device__ float  g_t1  [N_ATOMS * 128];
__device__ float  g_d   [N_EDGES];
__device__ float  g_sd  [N_EDGES];
__device__ int    g_ssrc[N_EDGES];
__device__ int    g_counts[N_ATOMS];
__device__ int    g_start [N_ATOMS];
__device__ int    g_cursor[N_ATOMS];
__device__ __half g_table[3 * TBL * 128];

__device__ __forceinline__ float sspf(float x) {
    return fmaxf(x, 0.0f) + log1pf(expf(-fabsf(x))) - LN2F;
}

__device__ __forceinline__ void tf32split(float x, float& hi, float& lo) {
    unsigned int h;
    asm("cvt.rna.tf32.f32 %0, %1;" : "=r"(h) : "f"(x));
    hi = __uint_as_float(h);
    float l = x - hi;
    unsigned int l2;
    asm("cvt.rna.tf32.f32 %0, %1;" : "=r"(l2) : "f"(l));
    lo = __uint_as_float(l2);
}

__device__ __forceinline__ void mma_tf32(float* d, const unsigned int* a, const unsigned int* b) {
    asm volatile(
        "mma.sync.aligned.m16n8k8.row.col.f32.tf32.tf32.f32 "
        "{%0,%1,%2,%3}, {%4,%5,%6,%7}, {%8,%9}, {%0,%1,%2,%3};\n"
        : "+f"(d[0]), "+f"(d[1]), "+f"(d[2]), "+f"(d[3])
        : "r"(a[0]), "r"(a[1]), "r"(a[2]), "r"(a[3]), "r"(b[0]), "r"(b[1]));
}

// ---------------- init ----------------
__global__ void k_init(const int* __restrict__ r, const float* __restrict__ embed,
                       float* __restrict__ out, int out_size) {
    int idx = blockIdx.x * blockDim.x + threadIdx.x;
    if (idx < N_ATOMS * 32) {
        int atom = idx >> 5, j = idx & 31;
        ((float4*)g_h)[atom * 32 + j] = ((const float4*)embed)[(size_t)r[atom] * 32 + j];
    }
    if (idx < N_ATOMS) g_counts[idx] = 0;
    if (idx < out_size) out[idx] = 0.0f;
}

// ---------------- edges: distances + dst histogram ----------------
__global__ void k_edges(const int* __restrict__ a, const float* __restrict__ xyz) {
    int e = blockIdx.x * blockDim.x + threadIdx.x;
    if (e >= N_EDGES) return;
    int d0 = a[2 * e], s0 = a[2 * e + 1];
    float dx = xyz[3 * d0 + 0] - xyz[3 * s0 + 0];
    float dy = xyz[3 * d0 + 1] - xyz[3 * s0 + 1];
    float dz = xyz[3 * d0 + 2] - xyz[3 * s0 + 2];
    g_d[e] = sqrtf(dx * dx + dy * dy + dz * dz + 1e-12f);
    atomicAdd(&g_counts[d0], 1);
}

// ---------------- single-block exclusive scan ----------------
__global__ __launch_bounds__(1024) void k_scan() {
    __shared__ int sh[1024];
    __shared__ int carry;
    int t = threadIdx.x;
    if (t == 0) carry = 0;
    for (int base = 0; base < N_ATOMS; base += 1024) {
        int i = base + t;
        int v = (i < N_ATOMS) ? g_counts[i] : 0;
        sh[t] = v;
        __syncthreads();
        #pragma unroll
        for (int off = 1; off < 1024; off <<= 1) {
            int x = (t >= off) ? sh[t - off] : 0;
            __syncthreads();
            sh[t] += x;
            __syncthreads();
        }
        int excl = carry + sh[t] - v;
        if (i < N_ATOMS) { g_start[i] = excl; g_cursor[i] = excl; }
        __syncthreads();
        if (t == 0) carry += sh[1023];
        __syncthreads();
    }
}

// ---------------- scatter edges into dst-sorted order ----------------
__global__ void k_scatter(const int* __restrict__ a) {
    int e = blockIdx.x * blockDim.x + threadIdx.x;
    if (e >= N_EDGES) return;
    int d0 = a[2 * e];
    int pos = atomicAdd(&g_cursor[d0], 1);
    g_ssrc[pos] = a[2 * e + 1];
    g_sd[pos] = g_d[e];
}

// ---------------- build W(d) tables (half output) ----------------
__global__ __launch_bounds__(128) void k_table(const float* __restrict__ fw1,
                                               const float* __restrict__ fb1,
                                               const float* __restrict__ fw2,
                                               const float* __restrict__ fb2) {
    int L = blockIdx.x / TBL, e = blockIdx.x % TBL;
    int j = threadIdx.x;
    __shared__ float gs[32];
    __shared__ float ts[128];
    float d = (float)e * (DMAXF / (float)(TBL - 1));
    if (j < 32) {
        float width = 5.0f / 31.0f;
        float off = (float)j * width;
        float x = d - off;
        gs[j] = expf((-0.5f / (width * width)) * x * x);
    }
    __syncthreads();
    const float* w1 = fw1 + (size_t)L * 32 * 128;
    float t = fb1[L * 128 + j];
    #pragma unroll
    for (int k = 0; k < 32; k++) t = fmaf(gs[k], w1[k * 128 + j], t);
    ts[j] = sspf(t);
    __syncthreads();
    const float* w2 = fw2 + (size_t)L * 128 * 128;
    float w = fb2[L * 128 + j];
    #pragma unroll 8
    for (int k = 0; k < 128; k++) w = fmaf(ts[k], w2[k * 128 + j], w);
    g_table[((size_t)L * TBL + e) * 128 + j] = __float2half_rn(w);
}

// ---------------- aggregation: one warp per atom, fp16 table+hf ----------------
__global__ __launch_bounds__(128) void k_agg(const __half* __restrict__ tbl) {
    int atom = blockIdx.x * 4 + threadIdx.y;
    int j = threadIdx.x;               // 0..31 -> 4 features each
    int s = g_start[atom], c = g_counts[atom];
    float4 acc = make_float4(0.f, 0.f, 0.f, 0.f);
    const uint2* hf2 = (const uint2*)g_hf;      // 4 halves per uint2, 32 per row
    const uint2* t2  = (const uint2*)tbl;
    #pragma unroll 2
    for (int e = 0; e < c; e++) {
        int src = __ldg(&g_ssrc[s + e]);
        float d = __ldg(&g_sd[s + e]);
        float u = fminf(d * ((float)(TBL - 1) / DMAXF), (float)(TBL - 1) - 1e-3f);
        int i0 = (int)u;
        float f = u - (float)i0;
        uint2 w0u = t2[(size_t)i0 * 32 + j];
        uint2 w1u = t2[(size_t)i0 * 32 + 32 + j];
        uint2 hvu = hf2[(size_t)src * 32 + j];
        float2 w0a = __half22float2(*(const __half2*)&w0u.x);
        float2 w0b = __half22float2(*(const __half2*)&w0u.y);
        float2 w1a = __half22float2(*(const __half2*)&w1u.x);
        float2 w1b = __half22float2(*(const __half2*)&w1u.y);
        float2 ha  = __half22float2(*(const __half2*)&hvu.x);
        float2 hb  = __half22float2(*(const __half2*)&hvu.y);
        acc.x += ha.x * fmaf(f, w1a.x - w0a.x, w0a.x);
        acc.y += ha.y * fmaf(f, w1a.y - w0a.y, w0a.y);
        acc.z += hb.x * fmaf(f, w1b.x - w0b.x, w0b.x);
        acc.w += hb.y * fmaf(f, w1b.y - w0b.y, w0b.y);
    }
    ((float4*)g_agg)[atom * 32 + j] = acc;
}

// ---------------- 3xTF32 tensor-core GEMM: C[M,128] = act(A@W + b) (+C | ->half) ----------------
// block 128x128, 8 warps (2x4), warp tile 64x32, mma m16n8k8
template <int ACT, int RES, int OUTH>
__global__ __launch_bounds__(256) void k_gemm_tc(const float* __restrict__ A,
                                                 const float* __restrict__ W,
                                                 const float* __restrict__ bias,
                                                 float* __restrict__ C,
                                                 __half* __restrict__ Ch, int M) {
    __shared__ float Ah[128 * 20], Al[128 * 20];     // stride 20 (bank-clean)
    __shared__ float Wh[KC * 136], Wl[KC * 136];     // stride 136 (bank-clean)
    __shared__ float bs[128];
    int tid = threadIdx.x;
    int lane = tid & 31, wid = tid >> 5;
    int wr = wid >> 2, wc = wid & 3;
    int row0 = blockIdx.x * 128;
    float acc[4][4][4];
    #pragma unroll
    for (int i = 0; i < 4; i++)
        #pragma unroll
        for (int jf = 0; jf < 4; jf++)
            #pragma unroll
            for (int q = 0; q < 4; q++) acc[i][jf][q] = 0.0f;
    if (tid < 128) bs[tid] = bias[tid];

    for (int kt = 0; kt < 128; kt += KC) {
        // stage A chunk [128 x 16] as tf32 hi/lo
        {
            int ar = tid >> 1;
            int ac = (tid & 1) * 8;
            #pragma unroll
            for (int h = 0; h < 2; h++) {
                float4 v = make_float4(0.f, 0.f, 0.f, 0.f);
                if (row0 + ar < M)
                    v = *(const float4*)(A + (size_t)(row0 + ar) * 128 + kt + ac + h * 4);
                float xs[4] = {v.x, v.y, v.z, v.w};
                #pragma unroll
                for (int q = 0; q < 4; q++) {
                    float hi, lo;
                    tf32split(xs[q], hi, lo);
                    Ah[ar * 20 + ac + h * 4 + q] = hi;
                    Al[ar * 20 + ac + h * 4 + q] = lo;
                }
            }
        }
        // stage W chunk [16 x 128] as tf32 hi/lo
        {
            int wkr = tid >> 4;            // 0..15
            int wcn = (tid & 15) * 8;
            #pragma unroll
            for (int h = 0; h < 2; h++) {
                float4 v = *(const float4*)(W + (size_t)(kt + wkr) * 128 + wcn + h * 4);
                float xs[4] = {v.x, v.y, v.z, v.w};
                #pragma unroll
                for (int q = 0; q < 4; q++) {
                    float hi, lo;
                    tf32split(xs[q], hi, lo);
                    Wh[wkr * 136 + wcn + h * 4 + q] = hi;
                    Wl[wkr * 136 + wcn + h * 4 + q] = lo;
                }
            }
        }
        __syncthreads();
        #pragma unroll
        for (int ks = 0; ks < KC; ks += 8) {
            unsigned int a_hi[4][4], a_lo[4][4], b_hi[4][2], b_lo[4][2];
            #pragma unroll
            for (int i = 0; i < 4; i++) {
                int r = wr * 64 + i * 16 + (lane >> 2);
                int k = ks + (lane & 3);
                a_hi[i][0] = __float_as_uint(Ah[r * 20 + k]);
                a_hi[i][1] = __float_as_uint(Ah[(r + 8) * 20 + k]);
                a_hi[i][2] = __float_as_uint(Ah[r * 20 + k + 4]);
                a_hi[i][3] = __float_as_uint(Ah[(r + 8) * 20 + k + 4]);
                a_lo[i][0] = __float_as_uint(Al[r * 20 + k]);
                a_lo[i][1] = __float_as_uint(Al[(r + 8) * 20 + k]);
                a_lo[i][2] = __float_as_uint(Al[r * 20 + k + 4]);
                a_lo[i][3] = __float_as_uint(Al[(r + 8) * 20 + k + 4]);
            }
            #pragma unroll
            for (int jf = 0; jf < 4; jf++) {
                int n = wc * 32 + jf * 8 + (lane >> 2);
                int k = ks + (lane & 3);
                b_hi[jf][0] = __float_as_uint(Wh[k * 136 + n]);
                b_hi[jf][1] = __float_as_uint(Wh[(k + 4) * 136 + n]);
                b_lo[jf][0] = __float_as_uint(Wl[k * 136 + n]);
                b_lo[jf][1] = __float_as_uint(Wl[(k + 4) * 136 + n]);
            }
            #pragma unroll
            for (int i = 0; i < 4; i++)
                #pragma unroll
                for (int jf = 0; jf < 4; jf++) {
                    mma_tf32(acc[i][jf], a_hi[i], b_hi[jf]);
                    mma_tf32(acc[i][jf], a_hi[i], b_lo[jf]);
                    mma_tf32(acc[i][jf], a_lo[i], b_hi[jf]);
                }
        }
        __syncthreads();
    }

    // epilogue
    #pragma unroll
    for (int i = 0; i < 4; i++) {
        int rbase = row0 + wr * 64 + i * 16 + (lane >> 2);
        #pragma unroll
        for (int jf = 0; jf < 4; jf++) {
            int n = wc * 32 + jf * 8 + 2 * (lane & 3);
            #pragma unroll
            for (int hh = 0; hh < 2; hh++) {
                int r = rbase + hh * 8;
                if (r >= M) continue;
                float v0 = acc[i][jf][hh * 2 + 0] + bs[n];
                float v1 = acc[i][jf][hh * 2 + 1] + bs[n + 1];
                if (ACT) { v0 = sspf(v0); v1 = sspf(v1); }
                if (OUTH) {
                    *(__half2*)(Ch + (size_t)r * 128 + n) = __floats2half2_rn(v0, v1);
                } else {
                    float* cp = C + (size_t)r * 128 + n;
                    if (RES) { v0 += cp[0]; v1 += cp[1]; }
                    float2 st; st.x = v0; st.y = v1;
                    *(float2*)cp = st;
                }
            }
        }
    }
}

// ---------------- readout ----------------
__global__ __launch_bounds__(256) void k_readout(const float* __restrict__ h,
                                                 const float* __restrict__ aw1,
                                                 const float* __restrict__ ab1,
                                                 const float* __restrict__ aw2,
                                                 const float* __restrict__ ab2,
                                                 float* __restrict__ out,
                                                 const int* __restrict__ nper) {
    __shared__ float w1s[128 * 64];
    __shared__ float hs[4][128];
    __shared__ float red[4][2];
    int tid = threadIdx.x;
    int np = nper ? nper[0] : 5000;
    for (int i = tid; i < 128 * 64; i += 256) w1s[i] = aw1[i];
    int j = tid & 63;
    int al = tid >> 6;
    float w2 = aw2[j];
    float b1 = ab1[j];
    int atom0 = blockIdx.x * 32;
    for (int round = 0; round < 8; round++) {
        __syncthreads();
        for (int i = tid; i < 512; i += 256) {
            int aa = i >> 7, kk = i & 127;
            int ga = atom0 + round * 4 + aa;
            hs[aa][kk] = (ga < N_ATOMS) ? h[(size_t)ga * 128 + kk] : 0.0f;
        }
        __syncthreads();
        float t = b1;
        #pragma unroll 16
        for (int k = 0; k < 128; k++) t = fmaf(hs[al][k], w1s[k * 64 + j], t);
        t = sspf(t) * w2;
        #pragma unroll
        for (int off = 16; off; off >>= 1) t += __shfl_down_sync(0xffffffffu, t, off);
        if ((tid & 31) == 0) red[al][j >> 5] = t;
        __syncthreads();
        int atom = atom0 + round * 4 + al;
        if (j == 0 && atom < N_ATOMS) {
            float y = red[al][0] + red[al][1] + ab2[0];
            atomicAdd(&out[atom / np], y);
        }
    }
}

// ---------------- host ----------------
extern "C" void kernel_launch(void* const* d_in, const int* in_sizes, int n_in,
                              void* d_out, int out_size) {
    const int*   r   = (const int*)d_in[0];
    const float* xyz = (const float*)d_in[1];
    const int*   a   = (const int*)d_in[2];
    int base = 3;
    const int* nper = nullptr;
    if (n_in >= 19) { nper = (const int*)d_in[3]; base = 4; }
    const float* embed = (const float*)d_in[base + 0];
    const float* fw1   = (const float*)d_in[base + 1];
    const float* fb1   = (const float*)d_in[base + 2];
    const float* fw2   = (const float*)d_in[base + 3];
    const float* fb2   = (const float*)d_in[base + 4];
    const float* afw   = (const float*)d_in[base + 5];
    const float* afb   = (const float*)d_in[base + 6];
    const float* ow1   = (const float*)d_in[base + 7];
    const float* ob1   = (const float*)d_in[base + 8];
    const float* ow2   = (const float*)d_in[base + 9];
    const float* ob2   = (const float*)d_in[base + 10];
    const float* aw1   = (const float*)d_in[base + 11];
    const float* ab1   = (const float*)d_in[base + 12];
    const float* aw2   = (const float*)d_in[base + 13];
    const float* ab2   = (const float*)d_in[base + 14];
    float* out = (float*)d_out;

    float *ph, *pagg, *pt1;
    __half *phf, *ptbl;
    cudaGetSymbolAddress((void**)&ph,   g_h);
    cudaGetSymbolAddress((void**)&phf,  g_hf);
    cudaGetSymbolAddress((void**)&pagg, g_agg);
    cudaGetSymbolAddress((void**)&pt1,  g_t1);
    cudaGetSymbolAddress((void**)&ptbl, g_table);

    k_init<<<(N_ATOMS * 32 + 255) / 256, 256>>>(r, embed, out, out_size);
    k_edges<<<(N_EDGES + 255) / 256, 256>>>(a, xyz);
    k_scan<<<1, 1024>>>();
    k_scatter<<<(N_EDGES + 255) / 256, 256>>>(a);
    k_table<<<3 * TBL, 128>>>(fw1, fb1, fw2, fb2);

    int gemm_grid = (N_ATOMS + 127) / 128;
    for (int L = 0; L < 3; L++) {
        k_gemm_tc<0, 0, 1><<<gemm_grid, 256>>>(ph, afw + (size_t)L * 16384, afb + L * 128,
                                               nullptr, phf, N_ATOMS);
        k_agg<<<N_ATOMS / 4, dim3(32, 4)>>>(ptbl + (size_t)L * TBL * 128);
        k_gemm_tc<1, 0, 0><<<gemm_grid, 256>>>(pagg, ow1 + (size_t)L * 16384, ob1 + L * 128,
                                               pt1, nullptr, N_ATOMS);
        k_gemm_tc<0, 1, 0><<<gemm_grid, 256>>>(pt1, ow2 + (size_t)L * 16384, ob2 + L * 128,
                                               ph, nullptr, N_ATOMS);
    }
    k_readout<<<(N_ATOMS + 31) / 32, 256>>>(ph, aw1, ab1, aw2, ab2, out, nper);
}

// round 3
// speedup vs baseline: 1.3591x; 1.3481x over previous
#include <cuda_runtime.h>
#include <cuda_fp16.h>
#include <math.h>

#define N_ATOMS 50000
#define N_EDGES 800000
#define TBL 8192
#define DMAXF 14.0f
#define LN2F 0.6931471805599453f

// ---------------- device scratch ----------------
__device__ float  g_h   [N_ATOMS * 128];
__device__ __half g_hf  [N_ATOMS * 128];
__device__ float  g_agg [N_ATOMS * 128];
__device__ float  g_t1  [N_ATOMS * 128];
__device__ float  g_d   [N_EDGES];
__device__ float  g_sd  [N_EDGES];
__device__ int    g_ssrc[N_EDGES];
__device__ int    g_counts[N_ATOMS];
__device__ int    g_start [N_ATOMS];
__device__ int    g_cursor[N_ATOMS];
__device__ __half g_table[3 * TBL * 128];

__device__ __forceinline__ float sspf(float x) {
    return fmaxf(x, 0.0f) + log1pf(expf(-fabsf(x))) - LN2F;
}

__device__ __forceinline__ void mma_f16(float* d, const unsigned* a, const unsigned* b) {
    asm volatile(
        "mma.sync.aligned.m16n8k16.row.col.f32.f16.f16.f32 "
        "{%0,%1,%2,%3}, {%4,%5,%6,%7}, {%8,%9}, {%0,%1,%2,%3};\n"
        : "+f"(d[0]), "+f"(d[1]), "+f"(d[2]), "+f"(d[3])
        : "r"(a[0]), "r"(a[1]), "r"(a[2]), "r"(a[3]), "r"(b[0]), "r"(b[1]));
}

// ---------------- init ----------------
__global__ void k_init(const int* __restrict__ r, const float* __restrict__ embed,
                       float* __restrict__ out, int out_size) {
    int idx = blockIdx.x * blockDim.x + threadIdx.x;
    if (idx < N_ATOMS * 32) {
        int atom = idx >> 5, j = idx & 31;
        ((float4*)g_h)[atom * 32 + j] = ((const float4*)embed)[(size_t)r[atom] * 32 + j];
    }
    if (idx < N_ATOMS) g_counts[idx] = 0;
    if (idx < out_size) out[idx] = 0.0f;
}

// ---------------- edges: distances + dst histogram ----------------
__global__ void k_edges(const int* __restrict__ a, const float* __restrict__ xyz) {
    int e = blockIdx.x * blockDim.x + threadIdx.x;
    if (e >= N_EDGES) return;
    int d0 = a[2 * e], s0 = a[2 * e + 1];
    float dx = xyz[3 * d0 + 0] - xyz[3 * s0 + 0];
    float dy = xyz[3 * d0 + 1] - xyz[3 * s0 + 1];
    float dz = xyz[3 * d0 + 2] - xyz[3 * s0 + 2];
    g_d[e] = sqrtf(dx * dx + dy * dy + dz * dz + 1e-12f);
    atomicAdd(&g_counts[d0], 1);
}

// ---------------- shfl-based exclusive scan ----------------
__global__ __launch_bounds__(1024) void k_scan() {
    __shared__ int wsum[32];
    __shared__ int carry;
    __shared__ int tot;
    int t = threadIdx.x, lane = t & 31, w = t >> 5;
    if (t == 0) carry = 0;
    __syncthreads();
    for (int base = 0; base < N_ATOMS; base += 1024) {
        int i = base + t;
        int v = (i < N_ATOMS) ? g_counts[i] : 0;
        int incl = v;
        #pragma unroll
        for (int off = 1; off < 32; off <<= 1) {
            int x = __shfl_up_sync(0xffffffffu, incl, off);
            if (lane >= off) incl += x;
        }
        if (lane == 31) wsum[w] = incl;
        __syncthreads();
        if (w == 0) {
            int s = wsum[lane];
            int si = s;
            #pragma unroll
            for (int off = 1; off < 32; off <<= 1) {
                int x = __shfl_up_sync(0xffffffffu, si, off);
                if (lane >= off) si += x;
            }
            wsum[lane] = si - s;      // exclusive warp offsets
            if (lane == 31) tot = si;
        }
        __syncthreads();
        int excl = carry + wsum[w] + incl - v;
        if (i < N_ATOMS) { g_start[i] = excl; g_cursor[i] = excl; }
        __syncthreads();
        if (t == 0) carry += tot;
        __syncthreads();
    }
}

// ---------------- scatter edges into dst-sorted order ----------------
__global__ void k_scatter(const int* __restrict__ a) {
    int e = blockIdx.x * blockDim.x + threadIdx.x;
    if (e >= N_EDGES) return;
    int d0 = a[2 * e];
    int pos = atomicAdd(&g_cursor[d0], 1);
    g_ssrc[pos] = a[2 * e + 1];
    g_sd[pos] = g_d[e];
}

// ---------------- build W(d) tables: 16 entries/block, w2 via smem ----------------
#define TE 16
__global__ __launch_bounds__(256) void k_table(const float* __restrict__ fw1,
                                               const float* __restrict__ fb1,
                                               const float* __restrict__ fw2,
                                               const float* __restrict__ fb2) {
    __shared__ float gsm[TE][32];
    __shared__ float ts[TE][128];
    __shared__ float w2c[32][128];
    int tid = threadIdx.x;
    int L = blockIdx.x / (TBL / TE);
    int e0 = (blockIdx.x % (TBL / TE)) * TE;
    float width = 5.0f / 31.0f;
    float coeff = -0.5f / (width * width);
    // gaussians for 16 entries
    for (int i = tid; i < TE * 32; i += 256) {
        int e = i >> 5, k = i & 31;
        float d = (float)(e0 + e) * (DMAXF / (float)(TBL - 1));
        float x = d - (float)k * width;
        gsm[e][k] = expf(coeff * x * x);
    }
    __syncthreads();
    int j = tid & 127;
    int eh = tid >> 7;            // 0/1, entries eh*8..eh*8+7
    // phase 1: ts = ssp(g @ fw1 + fb1)
    {
        const float* w1 = fw1 + (size_t)L * 32 * 128;
        float b = fb1[L * 128 + j];
        float acc[8];
        #pragma unroll
        for (int q = 0; q < 8; q++) acc[q] = b;
        #pragma unroll 4
        for (int k = 0; k < 32; k++) {
            float w = w1[k * 128 + j];
            #pragma unroll
            for (int q = 0; q < 8; q++) acc[q] = fmaf(gsm[eh * 8 + q][k], w, acc[q]);
        }
        #pragma unroll
        for (int q = 0; q < 8; q++) ts[eh * 8 + q][j] = sspf(acc[q]);
    }
    __syncthreads();
    // phase 2: W = ts @ fw2 + fb2
    const float* w2 = fw2 + (size_t)L * 128 * 128;
    float o[8];
    {
        float b = fb2[L * 128 + j];
        #pragma unroll
        for (int q = 0; q < 8; q++) o[q] = b;
    }
    for (int kt = 0; kt < 4; kt++) {
        #pragma unroll
        for (int p = 0; p < 4; p++) {
            int idx = tid + p * 256;
            int row = idx >> 5, col = (idx & 31) * 4;
            *(float4*)&w2c[row][col] = *(const float4*)(w2 + (size_t)(kt * 32 + row) * 128 + col);
        }
        __syncthreads();
        #pragma unroll 4
        for (int k = 0; k < 32; k++) {
            float w = w2c[k][j];
            int kk = kt * 32 + k;
            #pragma unroll
            for (int q = 0; q < 8; q++) o[q] = fmaf(ts[eh * 8 + q][kk], w, o[q]);
        }
        __syncthreads();
    }
    #pragma unroll
    for (int q = 0; q < 8; q++)
        g_table[((size_t)L * TBL + e0 + eh * 8 + q) * 128 + j] = __float2half_rn(o[q]);
}

// ---------------- aggregation: one warp per atom, fp16 table+hf ----------------
__global__ __launch_bounds__(128) void k_agg(const __half* __restrict__ tbl) {
    int atom = blockIdx.x * 4 + threadIdx.y;
    int j = threadIdx.x;
    int s = g_start[atom], c = g_counts[atom];
    float4 acc = make_float4(0.f, 0.f, 0.f, 0.f);
    const uint2* hf2 = (const uint2*)g_hf;
    const uint2* t2  = (const uint2*)tbl;
    #pragma unroll 2
    for (int e = 0; e < c; e++) {
        int src = __ldg(&g_ssrc[s + e]);
        float d = __ldg(&g_sd[s + e]);
        float u = fminf(d * ((float)(TBL - 1) / DMAXF), (float)(TBL - 1) - 1e-3f);
        int i0 = (int)u;
        float f = u - (float)i0;
        uint2 w0u = t2[(size_t)i0 * 32 + j];
        uint2 w1u = t2[(size_t)i0 * 32 + 32 + j];
        uint2 hvu = hf2[(size_t)src * 32 + j];
        float2 w0a = __half22float2(*(const __half2*)&w0u.x);
        float2 w0b = __half22float2(*(const __half2*)&w0u.y);
        float2 w1a = __half22float2(*(const __half2*)&w1u.x);
        float2 w1b = __half22float2(*(const __half2*)&w1u.y);
        float2 ha  = __half22float2(*(const __half2*)&hvu.x);
        float2 hb  = __half22float2(*(const __half2*)&hvu.y);
        acc.x += ha.x * fmaf(f, w1a.x - w0a.x, w0a.x);
        acc.y += ha.y * fmaf(f, w1a.y - w0a.y, w0a.y);
        acc.z += hb.x * fmaf(f, w1b.x - w0b.x, w0b.x);
        acc.w += hb.y * fmaf(f, w1b.y - w0b.y, w0b.y);
    }
    ((float4*)g_agg)[atom * 32 + j] = acc;
}

// ---------------- fp16 tensor-core GEMM: C[M,128] = act(A@W + b) (+C | ->half) ----------------
// block tile 128x128, 8 warps (2x4), warp tile 64x32, mma m16n8k16, K chunked by 64
template <int ACT, int RES, int OUTH>
__global__ __launch_bounds__(256) void k_gemm_f16(const float* __restrict__ A,
                                                  const float* __restrict__ W,
                                                  const float* __restrict__ bias,
                                                  float* __restrict__ C,
                                                  __half* __restrict__ Ch, int M) {
    __shared__ __half As[128 * 72];   // [m][k], stride 72 halves
    __shared__ __half Ws[128 * 72];   // [n][k] transposed, stride 72
    __shared__ float bs[128];
    int tid = threadIdx.x;
    int lane = tid & 31, wid = tid >> 5;
    int wr = wid >> 2, wc = wid & 3;         // warp row 0/1 (x64), warp col 0..3 (x32)
    int g = lane >> 2, tig = lane & 3;
    int row0 = blockIdx.x * 128;
    float acc[4][4][4];
    #pragma unroll
    for (int i = 0; i < 4; i++)
        #pragma unroll
        for (int jf = 0; jf < 4; jf++)
            #pragma unroll
            for (int q = 0; q < 4; q++) acc[i][jf][q] = 0.0f;
    if (tid < 128) bs[tid] = bias[tid];

    for (int kt = 0; kt < 128; kt += 64) {
        // stage A chunk [128 rows x 64 k] -> half
        {
            int ar = tid >> 1;
            int k0 = (tid & 1) * 32;
            const float* ap = A + (size_t)(row0 + ar) * 128 + kt + k0;
            bool valid = (row0 + ar) < M;
            #pragma unroll
            for (int p = 0; p < 8; p++) {
                float4 v = make_float4(0.f, 0.f, 0.f, 0.f);
                if (valid) v = *(const float4*)(ap + p * 4);
                *(__half2*)&As[ar * 72 + k0 + p * 4]     = __floats2half2_rn(v.x, v.y);
                *(__half2*)&As[ar * 72 + k0 + p * 4 + 2] = __floats2half2_rn(v.z, v.w);
            }
        }
        // stage W chunk [64 k x 128 n] transposed -> Ws[n][k]
        {
            #pragma unroll
            for (int p = 0; p < 4; p++) {
                int idx = tid + p * 256;           // 0..1023
                int krow = idx >> 4;               // 0..63
                int nq = (idx & 15) * 8;
                const float* wp = W + (size_t)(kt + krow) * 128 + nq;
                float4 v0 = *(const float4*)wp;
                float4 v1 = *(const float4*)(wp + 4);
                Ws[(nq + 0) * 72 + krow] = __float2half_rn(v0.x);
                Ws[(nq + 1) * 72 + krow] = __float2half_rn(v0.y);
                Ws[(nq + 2) * 72 + krow] = __float2half_rn(v0.z);
                Ws[(nq + 3) * 72 + krow] = __float2half_rn(v0.w);
                Ws[(nq + 4) * 72 + krow] = __float2half_rn(v1.x);
                Ws[(nq + 5) * 72 + krow] = __float2half_rn(v1.y);
                Ws[(nq + 6) * 72 + krow] = __float2half_rn(v1.z);
                Ws[(nq + 7) * 72 + krow] = __float2half_rn(v1.w);
            }
        }
        __syncthreads();
        #pragma unroll
        for (int ks = 0; ks < 64; ks += 16) {
            unsigned af[4][4], bf[4][2];
            #pragma unroll
            for (int i = 0; i < 4; i++) {
                int r = wr * 64 + i * 16 + g;
                af[i][0] = *(const unsigned*)&As[r * 72 + ks + tig * 2];
                af[i][1] = *(const unsigned*)&As[(r + 8) * 72 + ks + tig * 2];
                af[i][2] = *(const unsigned*)&As[r * 72 + ks + tig * 2 + 8];
                af[i][3] = *(const unsigned*)&As[(r + 8) * 72 + ks + tig * 2 + 8];
            }
            #pragma unroll
            for (int jf = 0; jf < 4; jf++) {
                int n = wc * 32 + jf * 8 + g;
                bf[jf][0] = *(const unsigned*)&Ws[n * 72 + ks + tig * 2];
                bf[jf][1] = *(const unsigned*)&Ws[n * 72 + ks + tig * 2 + 8];
            }
            #pragma unroll
            for (int i = 0; i < 4; i++)
                #pragma unroll
                for (int jf = 0; jf < 4; jf++)
                    mma_f16(acc[i][jf], af[i], bf[jf]);
        }
        __syncthreads();
    }

    // epilogue
    #pragma unroll
    for (int i = 0; i < 4; i++) {
        int rbase = row0 + wr * 64 + i * 16 + g;
        #pragma unroll
        for (int jf = 0; jf < 4; jf++) {
            int n = wc * 32 + jf * 8 + 2 * tig;
            #pragma unroll
            for (int hh = 0; hh < 2; hh++) {
                int r = rbase + hh * 8;
                if (r >= M) continue;
                float v0 = acc[i][jf][hh * 2 + 0] + bs[n];
                float v1 = acc[i][jf][hh * 2 + 1] + bs[n + 1];
                if (ACT) { v0 = sspf(v0); v1 = sspf(v1); }
                if (OUTH) {
                    *(__half2*)(Ch + (size_t)r * 128 + n) = __floats2half2_rn(v0, v1);
                } else {
                    float* cp = C + (size_t)r * 128 + n;
                    if (RES) { v0 += cp[0]; v1 += cp[1]; }
                    float2 st; st.x = v0; st.y = v1;
                    *(float2*)cp = st;
                }
            }
        }
    }
}

// ---------------- readout ----------------
__global__ __launch_bounds__(256) void k_readout(const float* __restrict__ h,
                                                 const float* __restrict__ aw1,
                                                 const float* __restrict__ ab1,
                                                 const float* __restrict__ aw2,
                                                 const float* __restrict__ ab2,
                                                 float* __restrict__ out,
                                                 const int* __restrict__ nper) {
    __shared__ float w1s[128 * 64];
    __shared__ float hs[4][128];
    __shared__ float red[4][2];
    int tid = threadIdx.x;
    int np = nper ? nper[0] : 5000;
    for (int i = tid; i < 128 * 64; i += 256) w1s[i] = aw1[i];
    int j = tid & 63;
    int al = tid >> 6;
    float w2 = aw2[j];
    float b1 = ab1[j];
    int atom0 = blockIdx.x * 32;
    for (int round = 0; round < 8; round++) {
        __syncthreads();
        for (int i = tid; i < 512; i += 256) {
            int aa = i >> 7, kk = i & 127;
            int ga = atom0 + round * 4 + aa;
            hs[aa][kk] = (ga < N_ATOMS) ? h[(size_t)ga * 128 + kk] : 0.0f;
        }
        __syncthreads();
        float t = b1;
        #pragma unroll 16
        for (int k = 0; k < 128; k++) t = fmaf(hs[al][k], w1s[k * 64 + j], t);
        t = sspf(t) * w2;
        #pragma unroll
        for (int off = 16; off; off >>= 1) t += __shfl_down_sync(0xffffffffu, t, off);
        if ((tid & 31) == 0) red[al][j >> 5] = t;
        __syncthreads();
        int atom = atom0 + round * 4 + al;
        if (j == 0 && atom < N_ATOMS) {
            float y = red[al][0] + red[al][1] + ab2[0];
            atomicAdd(&out[atom / np], y);
        }
    }
}

// ---------------- host ----------------
extern "C" void kernel_launch(void* const* d_in, const int* in_sizes, int n_in,
                              void* d_out, int out_size) {
    const int*   r   = (const int*)d_in[0];
    const float* xyz = (const float*)d_in[1];
    const int*   a   = (const int*)d_in[2];
    int base = 3;
    const int* nper = nullptr;
    if (n_in >= 19) { nper = (const int*)d_in[3]; base = 4; }
    const float* embed = (const float*)d_in[base + 0];
    const float* fw1   = (const float*)d_in[base + 1];
    const float* fb1   = (const float*)d_in[base + 2];
    const float* fw2   = (const float*)d_in[base + 3];
    const float* fb2   = (const float*)d_in[base + 4];
    const float* afw   = (const float*)d_in[base + 5];
    const float* afb   = (const float*)d_in[base + 6];
    const float* ow1   = (const float*)d_in[base + 7];
    const float* ob1   = (const float*)d_in[base + 8];
    const float* ow2   = (const float*)d_in[base + 9];
    const float* ob2   = (const float*)d_in[base + 10];
    const float* aw1   = (const float*)d_in[base + 11];
    const float* ab1   = (const float*)d_in[base + 12];
    const float* aw2   = (const float*)d_in[base + 13];
    const float* ab2   = (const float*)d_in[base + 14];
    float* out = (float*)d_out;

    float *ph, *pagg, *pt1;
    __half *phf, *ptbl;
    cudaGetSymbolAddress((void**)&ph,   g_h);
    cudaGetSymbolAddress((void**)&phf,  g_hf);
    cudaGetSymbolAddress((void**)&pagg, g_agg);
    cudaGetSymbolAddress((void**)&pt1,  g_t1);
    cudaGetSymbolAddress((void**)&ptbl, g_table);

    k_init<<<(N_ATOMS * 32 + 255) / 256, 256>>>(r, embed, out, out_size);
    k_edges<<<(N_EDGES + 255) / 256, 256>>>(a, xyz);
    k_scan<<<1, 1024>>>();
    k_scatter<<<(N_EDGES + 255) / 256, 256>>>(a);
    k_table<<<3 * (TBL / TE), 256>>>(fw1, fb1, fw2, fb2);

    int gemm_grid = (N_ATOMS + 127) / 128;
    for (int L = 0; L < 3; L++) {
        k_gemm_f16<0, 0, 1><<<gemm_grid, 256>>>(ph, afw + (size_t)L * 16384, afb + L * 128,
                                                nullptr, phf, N_ATOMS);
        k_agg<<<N_ATOMS / 4, dim3(32, 4)>>>(ptbl + (size_t)L * TBL * 128);
        k_gemm_f16<1, 0, 0><<<gemm_grid, 256>>>(pagg, ow1 + (size_t)L * 16384, ob1 + L * 128,
                                                pt1, nullptr, N_ATOMS);
        k_gemm_f16<0, 1, 0><<<gemm_grid, 256>>>(pt1, ow2 + (size_t)L * 16384, ob2 + L * 128,
                                                ph, nullptr, N_ATOMS);
    }
    k_readout<<<(N_ATOMS + 31) / 32, 256>>>(ph, aw1, ab1, aw2, ab2, out, nper);
}

// round 5
// speedup vs baseline: 1.4730x; 1.0839x over previous
#include <cuda_runtime.h>
#include <cuda_fp16.h>
#include <math.h>

#define N_ATOMS 50000
#define N_EDGES 800000
#define TBL 16384
#define DMAXF 14.0f
#define LN2F 0.6931471805599453f

// ---------------- device scratch ----------------
__device__ float  g_h   [N_ATOMS * 128];
__device__ __half g_hf  [N_ATOMS * 128];
__device__ float  g_agg [N_ATOMS * 128];
__device__ float  g_d   [N_EDGES];
__device__ int2   g_meta[N_EDGES];
__device__ int    g_counts[N_ATOMS];
__device__ int    g_start [N_ATOMS];
__device__ int    g_cursor[N_ATOMS];
__device__ float  g_ts   [3 * TBL * 128];
__device__ __half g_table[3 * TBL * 128];
__device__ float  g_w1pad[128 * 128];
__device__ float  g_b1pad[128];

__device__ __forceinline__ float sspf(float x) {
    return fmaxf(x, 0.0f) + log1pf(expf(-fabsf(x))) - LN2F;
}

__device__ __forceinline__ void mma_f16(float* d, const unsigned* a, const unsigned* b) {
    asm volatile(
        "mma.sync.aligned.m16n8k16.row.col.f32.f16.f16.f32 "
        "{%0,%1,%2,%3}, {%4,%5,%6,%7}, {%8,%9}, {%0,%1,%2,%3};\n"
        : "+f"(d[0]), "+f"(d[1]), "+f"(d[2]), "+f"(d[3])
        : "r"(a[0]), "r"(a[1]), "r"(a[2]), "r"(a[3]), "r"(b[0]), "r"(b[1]));
}

// ---------------- init ----------------
__global__ void k_init(const int* __restrict__ r, const float* __restrict__ embed,
                       float* __restrict__ out, int out_size) {
    int idx = blockIdx.x * blockDim.x + threadIdx.x;
    if (idx < N_ATOMS * 32) {
        int atom = idx >> 5, j = idx & 31;
        ((float4*)g_h)[atom * 32 + j] = ((const float4*)embed)[(size_t)r[atom] * 32 + j];
    }
    if (idx < N_ATOMS) g_counts[idx] = 0;
    if (idx < out_size) out[idx] = 0.0f;
}

// ---------------- edges: distances + dst histogram ----------------
__global__ void k_edges(const int* __restrict__ a, const float* __restrict__ xyz) {
    int e = blockIdx.x * blockDim.x + threadIdx.x;
    if (e >= N_EDGES) return;
    int d0 = a[2 * e], s0 = a[2 * e + 1];
    float dx = xyz[3 * d0 + 0] - xyz[3 * s0 + 0];
    float dy = xyz[3 * d0 + 1] - xyz[3 * s0 + 1];
    float dz = xyz[3 * d0 + 2] - xyz[3 * s0 + 2];
    g_d[e] = sqrtf(dx * dx + dy * dy + dz * dz + 1e-12f);
    atomicAdd(&g_counts[d0], 1);
}

// ---------------- shfl-based exclusive scan ----------------
__global__ __launch_bounds__(1024) void k_scan() {
    __shared__ int wsum[32];
    __shared__ int carry;
    __shared__ int tot;
    int t = threadIdx.x, lane = t & 31, w = t >> 5;
    if (t == 0) carry = 0;
    __syncthreads();
    for (int base = 0; base < N_ATOMS; base += 1024) {
        int i = base + t;
        int v = (i < N_ATOMS) ? g_counts[i] : 0;
        int incl = v;
        #pragma unroll
        for (int off = 1; off < 32; off <<= 1) {
            int x = __shfl_up_sync(0xffffffffu, incl, off);
            if (lane >= off) incl += x;
        }
        if (lane == 31) wsum[w] = incl;
        __syncthreads();
        if (w == 0) {
            int s = wsum[lane];
            int si = s;
            #pragma unroll
            for (int off = 1; off < 32; off <<= 1) {
                int x = __shfl_up_sync(0xffffffffu, si, off);
                if (lane >= off) si += x;
            }
            wsum[lane] = si - s;
            if (lane == 31) tot = si;
        }
        __syncthreads();
        int excl = carry + wsum[w] + incl - v;
        if (i < N_ATOMS) { g_start[i] = excl; g_cursor[i] = excl; }
        __syncthreads();
        if (t == 0) carry += tot;
        __syncthreads();
    }
}

// ---------------- scatter edges into dst-sorted order, pack (src, d) ----------------
__global__ void k_scatter(const int* __restrict__ a) {
    int e = blockIdx.x * blockDim.x + threadIdx.x;
    if (e >= N_EDGES) return;
    int d0 = a[2 * e];
    int pos = atomicAdd(&g_cursor[d0], 1);
    g_meta[pos] = make_int2(a[2 * e + 1], __float_as_int(g_d[e]));
}

// ---------------- ts = ssp(g @ fw1 + fb1) for all table entries, all layers ----------------
__global__ __launch_bounds__(256) void k_ts(const float* __restrict__ fw1,
                                            const float* __restrict__ fb1) {
    __shared__ float gsm[16][32];
    int tid = threadIdx.x;
    int L = blockIdx.x / (TBL / 16);
    int e0 = (blockIdx.x % (TBL / 16)) * 16;
    float width = 5.0f / 31.0f;
    float coeff = -0.5f / (width * width);
    for (int i = tid; i < 16 * 32; i += 256) {
        int e = i >> 5, k = i & 31;
        float d = (float)(e0 + e) * (DMAXF / (float)(TBL - 1));
        float x = d - (float)k * width;
        gsm[e][k] = expf(coeff * x * x);
    }
    __syncthreads();
    int j = tid & 127;
    int eh = tid >> 7;
    const float* w1 = fw1 + (size_t)L * 32 * 128;
    float b = fb1[L * 128 + j];
    float acc[8];
    #pragma unroll
    for (int q = 0; q < 8; q++) acc[q] = b;
    #pragma unroll 4
    for (int k = 0; k < 32; k++) {
        float w = w1[k * 128 + j];
        #pragma unroll
        for (int q = 0; q < 8; q++) acc[q] = fmaf(gsm[eh * 8 + q][k], w, acc[q]);
    }
    #pragma unroll
    for (int q = 0; q < 8; q++)
        g_ts[((size_t)L * TBL + e0 + eh * 8 + q) * 128 + j] = sspf(acc[q]);
}

// ---------------- pad readout weights to 128 wide (ssp(0)=0 makes this exact) ----------------
__global__ void k_pad(const float* __restrict__ aw1, const float* __restrict__ ab1) {
    int i = blockIdx.x * 256 + threadIdx.x;
    if (i < 128 * 128) {
        int k = i >> 7, j = i & 127;
        g_w1pad[i] = (j < 64) ? aw1[k * 64 + j] : 0.0f;
    }
    if (i < 128) g_b1pad[i] = (i < 64) ? ab1[i] : 0.0f;
}

// ---------------- aggregation: nearest-neighbor table, one warp per atom ----------------
__global__ __launch_bounds__(128) void k_agg(const __half* __restrict__ tbl) {
    int atom = blockIdx.x * 4 + threadIdx.y;
    int j = threadIdx.x;
    int s = g_start[atom], c = g_counts[atom];
    float4 acc = make_float4(0.f, 0.f, 0.f, 0.f);
    const uint2* hf2 = (const uint2*)g_hf;
    const uint2* t2  = (const uint2*)tbl;
    const int2* meta = (const int2*)g_meta;
    #pragma unroll 4
    for (int e = 0; e < c; e++) {
        int2 m = __ldg(&meta[s + e]);
        float d = __int_as_float(m.y);
        float u = d * ((float)(TBL - 1) / DMAXF);
        int i0 = (int)(u + 0.5f);
        i0 = min(i0, TBL - 1);
        uint2 wu = __ldg(&t2[(size_t)i0 * 32 + j]);
        uint2 hu = __ldg(&hf2[(size_t)m.x * 32 + j]);
        float2 wa = __half22float2(*(const __half2*)&wu.x);
        float2 wb = __half22float2(*(const __half2*)&wu.y);
        float2 ha = __half22float2(*(const __half2*)&hu.x);
        float2 hb = __half22float2(*(const __half2*)&hu.y);
        acc.x = fmaf(ha.x, wa.x, acc.x);
        acc.y = fmaf(ha.y, wa.y, acc.y);
        acc.z = fmaf(hb.x, wb.x, acc.z);
        acc.w = fmaf(hb.y, wb.y, acc.w);
    }
    ((float4*)g_agg)[atom * 32 + j] = acc;
}

// ================= shared GEMM building blocks =================
__device__ __forceinline__ void stage_A_chunk(const float* __restrict__ A, __half* As,
                                              int row0, int c, int M, int tid) {
    int ar = tid >> 1;
    int k0 = (tid & 1) * 32;
    const float* ap = A + (size_t)(row0 + ar) * 128 + c * 64 + k0;
    bool valid = (row0 + ar) < M;
    #pragma unroll
    for (int p = 0; p < 8; p++) {
        float4 v = make_float4(0.f, 0.f, 0.f, 0.f);
        if (valid) v = *(const float4*)(ap + p * 4);
        *(__half2*)&As[ar * 72 + k0 + p * 4]     = __floats2half2_rn(v.x, v.y);
        *(__half2*)&As[ar * 72 + k0 + p * 4 + 2] = __floats2half2_rn(v.z, v.w);
    }
}

__device__ __forceinline__ void stage_W_chunk(const float* __restrict__ W, __half* Ws,
                                              int c, int tid) {
    #pragma unroll
    for (int p = 0; p < 4; p++) {
        int idx = tid + p * 256;
        int krow = idx >> 4;
        int nq = (idx & 15) * 8;
        const float* wp = W + (size_t)(c * 64 + krow) * 128 + nq;
        float4 v0 = *(const float4*)wp;
        float4 v1 = *(const float4*)(wp + 4);
        Ws[(nq + 0) * 72 + krow] = __float2half_rn(v0.x);
        Ws[(nq + 1) * 72 + krow] = __float2half_rn(v0.y);
        Ws[(nq + 2) * 72 + krow] = __float2half_rn(v0.z);
        Ws[(nq + 3) * 72 + krow] = __float2half_rn(v0.w);
        Ws[(nq + 4) * 72 + krow] = __float2half_rn(v1.x);
        Ws[(nq + 5) * 72 + krow] = __float2half_rn(v1.y);
        Ws[(nq + 6) * 72 + krow] = __float2half_rn(v1.z);
        Ws[(nq + 7) * 72 + krow] = __float2half_rn(v1.w);
    }
}

__device__ __forceinline__ void mma_chunk(const __half* As, const __half* Ws,
                                          float acc[4][4][4], int wr, int wc, int g, int tig) {
    #pragma unroll
    for (int ks = 0; ks < 64; ks += 16) {
        unsigned af[4][4], bf[4][2];
        #pragma unroll
        for (int i = 0; i < 4; i++) {
            int r = wr * 64 + i * 16 + g;
            af[i][0] = *(const unsigned*)&As[r * 72 + ks + tig * 2];
            af[i][1] = *(const unsigned*)&As[(r + 8) * 72 + ks + tig * 2];
            af[i][2] = *(const unsigned*)&As[r * 72 + ks + tig * 2 + 8];
            af[i][3] = *(const unsigned*)&As[(r + 8) * 72 + ks + tig * 2 + 8];
        }
        #pragma unroll
        for (int jf = 0; jf < 4; jf++) {
            int n = wc * 32 + jf * 8 + g;
            bf[jf][0] = *(const unsigned*)&Ws[n * 72 + ks + tig * 2];
            bf[jf][1] = *(const unsigned*)&Ws[n * 72 + ks + tig * 2 + 8];
        }
        #pragma unroll
        for (int i = 0; i < 4; i++)
            #pragma unroll
            for (int jf = 0; jf < 4; jf++)
                mma_f16(acc[i][jf], af[i], bf[jf]);
    }
}

#define ZERO_ACC(acc) { _Pragma("unroll") for (int i = 0; i < 4; i++) _Pragma("unroll") \
    for (int jf = 0; jf < 4; jf++) _Pragma("unroll") for (int q = 0; q < 4; q++) acc[i][jf][q] = 0.0f; }

// ---------------- standalone fp16 TC GEMM (used for hf0, table build, readout) ----------------
template <int ACT, int OUTH>
__global__ __launch_bounds__(256) void k_gemm_f16(const float* __restrict__ A,
                                                  const float* __restrict__ W,
                                                  const float* __restrict__ bias,
                                                  float* __restrict__ C,
                                                  __half* __restrict__ Ch, int M) {
    __shared__ __half As[128 * 72];
    __shared__ __half Ws[128 * 72];
    __shared__ float bs[128];
    int tid = threadIdx.x;
    int lane = tid & 31, wid = tid >> 5;
    int wr = wid >> 2, wc = wid & 3;
    int g = lane >> 2, tig = lane & 3;
    int row0 = blockIdx.x * 128;
    float acc[4][4][4];
    ZERO_ACC(acc);
    if (tid < 128) bs[tid] = bias[tid];

    for (int c = 0; c < 2; c++) {
        stage_A_chunk(A, As, row0, c, M, tid);
        stage_W_chunk(W, Ws, c, tid);
        __syncthreads();
        mma_chunk(As, Ws, acc, wr, wc, g, tig);
        __syncthreads();
    }

    #pragma unroll
    for (int i = 0; i < 4; i++) {
        int rbase = row0 + wr * 64 + i * 16 + g;
        #pragma unroll
        for (int jf = 0; jf < 4; jf++) {
            int n = wc * 32 + jf * 8 + 2 * tig;
            #pragma unroll
            for (int hh = 0; hh < 2; hh++) {
                int r = rbase + hh * 8;
                if (r >= M) continue;
                float v0 = acc[i][jf][hh * 2 + 0] + bs[n];
                float v1 = acc[i][jf][hh * 2 + 1] + bs[n + 1];
                if (ACT) { v0 = sspf(v0); v1 = sspf(v1); }
                if (OUTH) {
                    *(__half2*)(Ch + (size_t)r * 128 + n) = __floats2half2_rn(v0, v1);
                } else {
                    float2 st; st.x = v0; st.y = v1;
                    *(float2*)(C + (size_t)r * 128 + n) = st;
                }
            }
        }
    }
}

// ---------------- fused layer kernel: t1=ssp(agg@W1+b1); h+=t1@W2+b2; hf=h@Wn+bn ----------------
template <int HASNEXT>
__global__ __launch_bounds__(256) void k_fused(const float* __restrict__ A,
                                               const float* __restrict__ W1,
                                               const float* __restrict__ b1,
                                               const float* __restrict__ W2,
                                               const float* __restrict__ b2,
                                               float* __restrict__ H,
                                               const float* __restrict__ Wn,
                                               const float* __restrict__ bn,
                                               __half* __restrict__ HF, int M) {
    extern __shared__ char dsm[];
    __half* As0 = (__half*)dsm;                 // 128*72 halves
    __half* As1 = (__half*)(dsm + 18432);
    __half* Ws  = (__half*)(dsm + 36864);
    float*  bs  = (float*)(dsm + 55296);        // [3][128]
    __half* Asc[2] = {As0, As1};
    int tid = threadIdx.x;
    int lane = tid & 31, wid = tid >> 5;
    int wr = wid >> 2, wc = wid & 3;
    int g = lane >> 2, tig = lane & 3;
    int row0 = blockIdx.x * 128;
    if (tid < 128) {
        bs[tid] = b1[tid];
        bs[128 + tid] = b2[tid];
        bs[256 + tid] = HASNEXT ? bn[tid] : 0.0f;
    }
    float acc[4][4][4];
    ZERO_ACC(acc);

    // mainloop1: acc = A @ W1
    for (int c = 0; c < 2; c++) {
        stage_A_chunk(A, Asc[c], row0, c, M, tid);
        stage_W_chunk(W1, Ws, c, tid);
        __syncthreads();
        mma_chunk(Asc[c], Ws, acc, wr, wc, g, tig);
        __syncthreads();
    }
    // epilogue1: t1 = ssp(acc + b1) -> As0/As1 (row-major [r][k])
    #pragma unroll
    for (int i = 0; i < 4; i++) {
        #pragma unroll
        for (int jf = 0; jf < 4; jf++) {
            int n = wc * 32 + jf * 8 + 2 * tig;
            #pragma unroll
            for (int hh = 0; hh < 2; hh++) {
                int rloc = wr * 64 + i * 16 + g + hh * 8;
                float v0 = sspf(acc[i][jf][hh * 2 + 0] + bs[n]);
                float v1 = sspf(acc[i][jf][hh * 2 + 1] + bs[n + 1]);
                *(__half2*)&Asc[n >> 6][rloc * 72 + (n & 63)] = __floats2half2_rn(v0, v1);
            }
        }
    }
    ZERO_ACC(acc);
    // mainloop2: acc = t1 @ W2
    for (int c = 0; c < 2; c++) {
        stage_W_chunk(W2, Ws, c, tid);
        __syncthreads();
        mma_chunk(Asc[c], Ws, acc, wr, wc, g, tig);
        __syncthreads();
    }
    // epilogue2: h += acc + b2 (global), and stash hnew -> As0/As1 for mainloop3
    #pragma unroll
    for (int i = 0; i < 4; i++) {
        #pragma unroll
        for (int jf = 0; jf < 4; jf++) {
            int n = wc * 32 + jf * 8 + 2 * tig;
            #pragma unroll
            for (int hh = 0; hh < 2; hh++) {
                int rloc = wr * 64 + i * 16 + g + hh * 8;
                int r = row0 + rloc;
                float v0 = acc[i][jf][hh * 2 + 0] + bs[128 + n];
                float v1 = acc[i][jf][hh * 2 + 1] + bs[128 + n + 1];
                if (r < M) {
                    float2 hold = *(const float2*)(H + (size_t)r * 128 + n);
                    v0 += hold.x; v1 += hold.y;
                    float2 st; st.x = v0; st.y = v1;
                    *(float2*)(H + (size_t)r * 128 + n) = st;
                }
                if (HASNEXT)
                    *(__half2*)&Asc[n >> 6][rloc * 72 + (n & 63)] = __floats2half2_rn(v0, v1);
            }
        }
    }
    if (HASNEXT) {
        ZERO_ACC(acc);
        // mainloop3: acc = hnew @ Wn
        for (int c = 0; c < 2; c++) {
            stage_W_chunk(Wn, Ws, c, tid);
            __syncthreads();
            mma_chunk(Asc[c], Ws, acc, wr, wc, g, tig);
            __syncthreads();
        }
        // epilogue3: hf = half(acc + bn)
        #pragma unroll
        for (int i = 0; i < 4; i++) {
            #pragma unroll
            for (int jf = 0; jf < 4; jf++) {
                int n = wc * 32 + jf * 8 + 2 * tig;
                #pragma unroll
                for (int hh = 0; hh < 2; hh++) {
                    int r = row0 + wr * 64 + i * 16 + g + hh * 8;
                    if (r >= M) continue;
                    float v0 = acc[i][jf][hh * 2 + 0] + bs[256 + n];
                    float v1 = acc[i][jf][hh * 2 + 1] + bs[256 + n + 1];
                    *(__half2*)(HF + (size_t)r * 128 + n) = __floats2half2_rn(v0, v1);
                }
            }
        }
    }
}

// ---------------- final reduce: y = t1row(0:64) . aw2 + ab2, block-sum ----------------
__global__ __launch_bounds__(128) void k_red(const float* __restrict__ t1,
                                             const float* __restrict__ aw2,
                                             const float* __restrict__ ab2,
                                             float* __restrict__ out,
                                             const int* __restrict__ nper) {
    int atom = blockIdx.x * 4 + (threadIdx.x >> 5);
    int lane = threadIdx.x & 31;
    int np = nper ? __ldg(nper) : 5000;
    float2 v = *(const float2*)(t1 + (size_t)atom * 128 + lane * 2);
    float s = v.x * __ldg(&aw2[lane * 2]) + v.y * __ldg(&aw2[lane * 2 + 1]);
    #pragma unroll
    for (int off = 16; off; off >>= 1) s += __shfl_down_sync(0xffffffffu, s, off);
    if (lane == 0) atomicAdd(&out[atom / np], s + __ldg(ab2));
}

// ---------------- host ----------------
extern "C" void kernel_launch(void* const* d_in, const int* in_sizes, int n_in,
                              void* d_out, int out_size) {
    const int*   r   = (const int*)d_in[0];
    const float* xyz = (const float*)d_in[1];
    const int*   a   = (const int*)d_in[2];
    int base = 3;
    const int* nper = nullptr;
    if (n_in >= 19) { nper = (const int*)d_in[3]; base = 4; }
    const float* embed = (const float*)d_in[base + 0];
    const float* fw1   = (const float*)d_in[base + 1];
    const float* fb1   = (const float*)d_in[base + 2];
    const float* fw2   = (const float*)d_in[base + 3];
    const float* fb2   = (const float*)d_in[base + 4];
    const float* afw   = (const float*)d_in[base + 5];
    const float* afb   = (const float*)d_in[base + 6];
    const float* ow1   = (const float*)d_in[base + 7];
    const float* ob1   = (const float*)d_in[base + 8];
    const float* ow2   = (const float*)d_in[base + 9];
    const float* ob2   = (const float*)d_in[base + 10];
    const float* aw1   = (const float*)d_in[base + 11];
    const float* ab1   = (const float*)d_in[base + 12];
    const float* aw2   = (const float*)d_in[base + 13];
    const float* ab2   = (const float*)d_in[base + 14];
    float* out = (float*)d_out;

    float *ph, *pagg, *pts, *pw1pad, *pb1pad;
    __half *phf, *ptbl;
    cudaGetSymbolAddress((void**)&ph,     g_h);
    cudaGetSymbolAddress((void**)&phf,    g_hf);
    cudaGetSymbolAddress((void**)&pagg,   g_agg);
    cudaGetSymbolAddress((void**)&pts,    g_ts);
    cudaGetSymbolAddress((void**)&ptbl,   g_table);
    cudaGetSymbolAddress((void**)&pw1pad, g_w1pad);
    cudaGetSymbolAddress((void**)&pb1pad, g_b1pad);

    const int FUSED_SMEM = 56832;
    cudaFuncSetAttribute(k_fused<1>, cudaFuncAttributeMaxDynamicSharedMemorySize, FUSED_SMEM);
    cudaFuncSetAttribute(k_fused<0>, cudaFuncAttributeMaxDynamicSharedMemorySize, FUSED_SMEM);

    k_init<<<(N_ATOMS * 32 + 255) / 256, 256>>>(r, embed, out, out_size);
    k_edges<<<(N_EDGES + 255) / 256, 256>>>(a, xyz);
    k_scan<<<1, 1024>>>();
    k_scatter<<<(N_EDGES + 255) / 256, 256>>>(a);
    k_ts<<<3 * (TBL / 16), 256>>>(fw1, fb1);
    for (int L = 0; L < 3; L++)
        k_gemm_f16<0, 1><<<TBL / 128, 256>>>(pts + (size_t)L * TBL * 128,
                                             fw2 + (size_t)L * 16384, fb2 + L * 128,
                                             nullptr, ptbl + (size_t)L * TBL * 128, TBL);
    k_pad<<<64, 256>>>(aw1, ab1);

    int gemm_grid = (N_ATOMS + 127) / 128;
    // initial hf = h @ afw0 + afb0
    k_gemm_f16<0, 1><<<gemm_grid, 256>>>(ph, afw, afb, nullptr, phf, N_ATOMS);
    for (int L = 0; L < 3; L++) {
        k_agg<<<N_ATOMS / 4, dim3(32, 4)>>>(ptbl + (size_t)L * TBL * 128);
        if (L < 2)
            k_fused<1><<<gemm_grid, 256, FUSED_SMEM>>>(
                pagg, ow1 + (size_t)L * 16384, ob1 + L * 128,
                ow2 + (size_t)L * 16384, ob2 + L * 128, ph,
                afw + (size_t)(L + 1) * 16384, afb + (L + 1) * 128, phf, N_ATOMS);
        else
            k_fused<0><<<gemm_grid, 256, FUSED_SMEM>>>(
                pagg, ow1 + (size_t)L * 16384, ob1 + L * 128,
                ow2 + (size_t)L * 16384, ob2 + L * 128, ph,
                nullptr, nullptr, nullptr, N_ATOMS);
    }
    // readout: t1 = ssp(h @ w1pad + b1pad) -> g_agg (fp32), then dot+reduce
    k_gemm_f16<1, 0><<<gemm_grid, 256>>>(ph, pw1pad, pb1pad, pagg, nullptr, N_ATOMS);
    k_red<<<N_ATOMS / 4, 128>>>(pagg, aw2, ab2, out, nper);
}

// round 7
// speedup vs baseline: 2.0302x; 1.3783x over previous
#include <cuda_runtime.h>
#include <cuda_fp16.h>
#include <math.h>

#define N_ATOMS 50000
#define N_EDGES 800000
#define TBL 16384
#define DMAXF 14.0f
#define LN2F 0.6931471805599453f

// ---------------- device scratch ----------------
__device__ float  g_h   [N_ATOMS * 128];
__device__ __half g_hf  [N_ATOMS * 128];
__device__ __half g_aggh[N_ATOMS * 128];
__device__ float  g_d   [N_EDGES];
__device__ int2   g_meta[N_EDGES];
__device__ int    g_counts[N_ATOMS];
__device__ int    g_start [N_ATOMS];
__device__ int    g_cursor[N_ATOMS];
__device__ float  g_ts   [3 * TBL * 128];
__device__ __half g_table[3 * TBL * 128];
__device__ __half g_whT  [13 * 128 * 128];   // [n][k] half weights: 0-2 ow1, 3-5 ow2, 6-8 afw, 9-11 fw2, 12 w1pad
__device__ float  g_b1pad[128];
__device__ float  g_aw2pad[128];

__device__ __forceinline__ float sspf(float x) {
    return fmaxf(x, 0.0f) + log1pf(expf(-fabsf(x))) - LN2F;
}

__device__ __forceinline__ void mma_f16(float* d, const unsigned* a, const unsigned* b) {
    asm volatile(
        "mma.sync.aligned.m16n8k16.row.col.f32.f16.f16.f32 "
        "{%0,%1,%2,%3}, {%4,%5,%6,%7}, {%8,%9}, {%0,%1,%2,%3};\n"
        : "+f"(d[0]), "+f"(d[1]), "+f"(d[2]), "+f"(d[3])
        : "r"(a[0]), "r"(a[1]), "r"(a[2]), "r"(a[3]), "r"(b[0]), "r"(b[1]));
}

// ---------------- init ----------------
__global__ void k_init(const int* __restrict__ r, const float* __restrict__ embed,
                       float* __restrict__ out, int out_size) {
    int idx = blockIdx.x * blockDim.x + threadIdx.x;
    if (idx < N_ATOMS * 32) {
        int atom = idx >> 5, j = idx & 31;
        ((float4*)g_h)[atom * 32 + j] = ((const float4*)embed)[(size_t)r[atom] * 32 + j];
    }
    if (idx < N_ATOMS) g_counts[idx] = 0;
    if (idx < out_size) out[idx] = 0.0f;
}

// ---------------- edges ----------------
__global__ void k_edges(const int* __restrict__ a, const float* __restrict__ xyz) {
    int e = blockIdx.x * blockDim.x + threadIdx.x;
    if (e >= N_EDGES) return;
    int d0 = a[2 * e], s0 = a[2 * e + 1];
    float dx = xyz[3 * d0 + 0] - xyz[3 * s0 + 0];
    float dy = xyz[3 * d0 + 1] - xyz[3 * s0 + 1];
    float dz = xyz[3 * d0 + 2] - xyz[3 * s0 + 2];
    g_d[e] = sqrtf(dx * dx + dy * dy + dz * dz + 1e-12f);
    atomicAdd(&g_counts[d0], 1);
}

// ---------------- exclusive scan ----------------
__global__ __launch_bounds__(1024) void k_scan() {
    __shared__ int wsum[32];
    __shared__ int carry;
    __shared__ int tot;
    int t = threadIdx.x, lane = t & 31, w = t >> 5;
    if (t == 0) carry = 0;
    __syncthreads();
    for (int base = 0; base < N_ATOMS; base += 1024) {
        int i = base + t;
        int v = (i < N_ATOMS) ? g_counts[i] : 0;
        int incl = v;
        #pragma unroll
        for (int off = 1; off < 32; off <<= 1) {
            int x = __shfl_up_sync(0xffffffffu, incl, off);
            if (lane >= off) incl += x;
        }
        if (lane == 31) wsum[w] = incl;
        __syncthreads();
        if (w == 0) {
            int s = wsum[lane];
            int si = s;
            #pragma unroll
            for (int off = 1; off < 32; off <<= 1) {
                int x = __shfl_up_sync(0xffffffffu, si, off);
                if (lane >= off) si += x;
            }
            wsum[lane] = si - s;
            if (lane == 31) tot = si;
        }
        __syncthreads();
        int excl = carry + wsum[w] + incl - v;
        if (i < N_ATOMS) { g_start[i] = excl; g_cursor[i] = excl; }
        __syncthreads();
        if (t == 0) carry += tot;
        __syncthreads();
    }
}

// ---------------- scatter ----------------
__global__ void k_scatter(const int* __restrict__ a) {
    int e = blockIdx.x * blockDim.x + threadIdx.x;
    if (e >= N_EDGES) return;
    int d0 = a[2 * e];
    int pos = atomicAdd(&g_cursor[d0], 1);
    g_meta[pos] = make_int2(a[2 * e + 1], __float_as_int(g_d[e]));
}

// ---------------- weight transpose+convert: fp32 [k][n] -> half [n][k] ----------------
__global__ void k_prep(const float* __restrict__ ow1, const float* __restrict__ ow2,
                       const float* __restrict__ afw, const float* __restrict__ fw2) {
    __shared__ float t[32][33];
    int mat = blockIdx.z;
    const float* src = (mat < 3) ? ow1 + (size_t)mat * 16384
                     : (mat < 6) ? ow2 + (size_t)(mat - 3) * 16384
                     : (mat < 9) ? afw + (size_t)(mat - 6) * 16384
                                 : fw2 + (size_t)(mat - 9) * 16384;
    __half* dst = g_whT + (size_t)mat * 16384;
    int k0 = blockIdx.y * 32, n0 = blockIdx.x * 32;
    int tx = threadIdx.x, ty = threadIdx.y;   // (32, 8)
    #pragma unroll
    for (int q = 0; q < 4; q++)
        t[ty + q * 8][tx] = src[(size_t)(k0 + ty + q * 8) * 128 + n0 + tx];
    __syncthreads();
    #pragma unroll
    for (int q = 0; q < 4; q++)
        dst[(size_t)(n0 + ty + q * 8) * 128 + k0 + tx] = __float2half_rn(t[tx][ty + q * 8]);
}

// ---------------- readout weight pad: aw1[128][64] -> slot 12 half [n=128][k=128] ----------------
__global__ void k_pad(const float* __restrict__ aw1, const float* __restrict__ ab1,
                      const float* __restrict__ aw2) {
    int i = blockIdx.x * 256 + threadIdx.x;
    if (i < 128 * 128) {
        int n = i >> 7, k = i & 127;
        g_whT[12 * 16384 + i] = __float2half_rn((n < 64) ? aw1[k * 64 + n] : 0.0f);
    }
    if (i < 128) {
        g_b1pad[i]  = (i < 64) ? ab1[i] : 0.0f;
        g_aw2pad[i] = (i < 64) ? aw2[i] : 0.0f;
    }
}

// ---------------- ts = ssp(g @ fw1 + fb1) ----------------
__global__ __launch_bounds__(256) void k_ts(const float* __restrict__ fw1,
                                            const float* __restrict__ fb1) {
    __shared__ float gsm[16][32];
    int tid = threadIdx.x;
    int L = blockIdx.x / (TBL / 16);
    int e0 = (blockIdx.x % (TBL / 16)) * 16;
    float width = 5.0f / 31.0f;
    float coeff = -0.5f / (width * width);
    for (int i = tid; i < 16 * 32; i += 256) {
        int e = i >> 5, k = i & 31;
        float d = (float)(e0 + e) * (DMAXF / (float)(TBL - 1));
        float x = d - (float)k * width;
        gsm[e][k] = expf(coeff * x * x);
    }
    __syncthreads();
    int j = tid & 127;
    int eh = tid >> 7;
    const float* w1 = fw1 + (size_t)L * 32 * 128;
    float b = fb1[L * 128 + j];
    float acc[8];
    #pragma unroll
    for (int q = 0; q < 8; q++) acc[q] = b;
    #pragma unroll 4
    for (int k = 0; k < 32; k++) {
        float w = w1[k * 128 + j];
        #pragma unroll
        for (int q = 0; q < 8; q++) acc[q] = fmaf(gsm[eh * 8 + q][k], w, acc[q]);
    }
    #pragma unroll
    for (int q = 0; q < 8; q++)
        g_ts[((size_t)L * TBL + e0 + eh * 8 + q) * 128 + j] = sspf(acc[q]);
}

// ---------------- aggregation: NN table, one warp per atom, half out ----------------
__global__ __launch_bounds__(256) void k_agg(const __half* __restrict__ tbl) {
    int atom = blockIdx.x * 8 + threadIdx.y;
    int j = threadIdx.x;
    int s = g_start[atom], c = g_counts[atom];
    float4 acc = make_float4(0.f, 0.f, 0.f, 0.f);
    const uint2* hf2 = (const uint2*)g_hf;
    const uint2* t2  = (const uint2*)tbl;
    const int2* meta = (const int2*)g_meta;
    #pragma unroll 4
    for (int e = 0; e < c; e++) {
        int2 m = __ldg(&meta[s + e]);
        float d = __int_as_float(m.y);
        float u = d * ((float)(TBL - 1) / DMAXF);
        int i0 = (int)(u + 0.5f);
        i0 = min(i0, TBL - 1);
        uint2 wu = __ldg(&t2[(size_t)i0 * 32 + j]);
        uint2 hu = __ldg(&hf2[(size_t)m.x * 32 + j]);
        float2 wa = __half22float2(*(const __half2*)&wu.x);
        float2 wb = __half22float2(*(const __half2*)&wu.y);
        float2 ha = __half22float2(*(const __half2*)&hu.x);
        float2 hb = __half22float2(*(const __half2*)&hu.y);
        acc.x = fmaf(ha.x, wa.x, acc.x);
        acc.y = fmaf(ha.y, wa.y, acc.y);
        acc.z = fmaf(hb.x, wb.x, acc.z);
        acc.w = fmaf(hb.y, wb.y, acc.w);
    }
    uint2 st;
    *(__half2*)&st.x = __floats2half2_rn(acc.x, acc.y);
    *(__half2*)&st.y = __floats2half2_rn(acc.z, acc.w);
    ((uint2*)g_aggh)[atom * 32 + j] = st;
}

// ================= GEMM building blocks =================
// A fp32 [m][128] -> half smem [m][k] stride 72 (with convert)
__device__ __forceinline__ void stage_A_f(const float* __restrict__ A, __half* As,
                                          int row0, int c, int M, int tid) {
    int ar = tid >> 1;
    int k0 = (tid & 1) * 32;
    const float* ap = A + (size_t)(row0 + ar) * 128 + c * 64 + k0;
    bool valid = (row0 + ar) < M;
    #pragma unroll
    for (int p = 0; p < 8; p++) {
        float4 v = make_float4(0.f, 0.f, 0.f, 0.f);
        if (valid) v = *(const float4*)(ap + p * 4);
        *(__half2*)&As[ar * 72 + k0 + p * 4]     = __floats2half2_rn(v.x, v.y);
        *(__half2*)&As[ar * 72 + k0 + p * 4 + 2] = __floats2half2_rn(v.z, v.w);
    }
}

// A half [m][128] -> smem copy
__device__ __forceinline__ void stage_A_h(const __half* __restrict__ Ah, __half* As,
                                          int row0, int c, int M, int tid) {
    #pragma unroll
    for (int p = 0; p < 4; p++) {
        int idx = tid + p * 256;
        int m = idx >> 3, k8 = (idx & 7) * 8;
        uint4 v = make_uint4(0, 0, 0, 0);
        if (row0 + m < M) v = *(const uint4*)(Ah + (size_t)(row0 + m) * 128 + c * 64 + k8);
        *(uint4*)&As[m * 72 + k8] = v;
    }
}

// W half [n][128] -> smem copy [n][k] stride 72
__device__ __forceinline__ void stage_W_h(const __half* __restrict__ Wh, __half* Ws,
                                          int c, int tid) {
    #pragma unroll
    for (int p = 0; p < 4; p++) {
        int idx = tid + p * 256;
        int n = idx >> 3, k8 = (idx & 7) * 8;
        *(uint4*)&Ws[n * 72 + k8] = *(const uint4*)(Wh + (size_t)n * 128 + c * 64 + k8);
    }
}

__device__ __forceinline__ void mma_chunk(const __half* As, const __half* Ws,
                                          float acc[4][4][4], int wr, int wc, int g, int tig) {
    #pragma unroll
    for (int ks = 0; ks < 64; ks += 16) {
        unsigned af[4][4], bf[4][2];
        #pragma unroll
        for (int i = 0; i < 4; i++) {
            int r = wr * 64 + i * 16 + g;
            af[i][0] = *(const unsigned*)&As[r * 72 + ks + tig * 2];
            af[i][1] = *(const unsigned*)&As[(r + 8) * 72 + ks + tig * 2];
            af[i][2] = *(const unsigned*)&As[r * 72 + ks + tig * 2 + 8];
            af[i][3] = *(const unsigned*)&As[(r + 8) * 72 + ks + tig * 2 + 8];
        }
        #pragma unroll
        for (int jf = 0; jf < 4; jf++) {
            int n = wc * 32 + jf * 8 + g;
            bf[jf][0] = *(const unsigned*)&Ws[n * 72 + ks + tig * 2];
            bf[jf][1] = *(const unsigned*)&Ws[n * 72 + ks + tig * 2 + 8];
        }
        #pragma unroll
        for (int i = 0; i < 4; i++)
            #pragma unroll
            for (int jf = 0; jf < 4; jf++)
                mma_f16(acc[i][jf], af[i], bf[jf]);
    }
}

#define ZERO_ACC(acc) { _Pragma("unroll") for (int i = 0; i < 4; i++) _Pragma("unroll") \
    for (int jf = 0; jf < 4; jf++) _Pragma("unroll") for (int q = 0; q < 4; q++) acc[i][jf][q] = 0.0f; }

// ---------------- generic GEMM: fp32-A, half-W; OUTH -> half out; RED -> fused readout ----------------
template <int OUTH, int RED>
__global__ __launch_bounds__(256) void k_gemm(const float* __restrict__ A,
                                              const __half* __restrict__ Wh,
                                              const float* __restrict__ bias,
                                              __half* __restrict__ Ch,
                                              const float* __restrict__ ab2,
                                              float* __restrict__ out,
                                              const int* __restrict__ nper, int M) {
    __shared__ __half As[128 * 72];
    __shared__ __half Ws[128 * 72];
    __shared__ float bs[128];
    __shared__ float aw2s[128];
    __shared__ float srow[128];
    int tid = threadIdx.x;
    int lane = tid & 31, wid = tid >> 5;
    int wr = wid >> 2, wc = wid & 3;
    int g = lane >> 2, tig = lane & 3;
    int row0 = blockIdx.x * 128;
    float acc[4][4][4];
    ZERO_ACC(acc);
    if (tid < 128) {
        bs[tid] = bias[tid];
        if (RED) { aw2s[tid] = g_aw2pad[tid]; srow[tid] = 0.0f; }
    }

    for (int c = 0; c < 2; c++) {
        stage_A_f(A, As, row0, c, M, tid);
        stage_W_h(Wh, Ws, c, tid);
        __syncthreads();
        mma_chunk(As, Ws, acc, wr, wc, g, tig);
        __syncthreads();
    }

    if (RED) {
        int np = nper ? __ldg(nper) : 5000;
        float ab2v = __ldg(ab2);
        #pragma unroll
        for (int i = 0; i < 4; i++) {
            #pragma unroll
            for (int hh = 0; hh < 2; hh++) {
                int rloc = wr * 64 + i * 16 + g + hh * 8;
                float s = 0.0f;
                #pragma unroll
                for (int jf = 0; jf < 4; jf++) {
                    int n = wc * 32 + jf * 8 + 2 * tig;
                    float v0 = sspf(acc[i][jf][hh * 2 + 0] + bs[n]);
                    float v1 = sspf(acc[i][jf][hh * 2 + 1] + bs[n + 1]);
                    s += v0 * aw2s[n] + v1 * aw2s[n + 1];
                }
                atomicAdd(&srow[rloc], s);
            }
        }
        __syncthreads();
        if (tid < 128) {
            int r = row0 + tid;
            if (r < M) atomicAdd(&out[r / np], srow[tid] + ab2v);
        }
    } else {
        #pragma unroll
        for (int i = 0; i < 4; i++) {
            int rbase = row0 + wr * 64 + i * 16 + g;
            #pragma unroll
            for (int jf = 0; jf < 4; jf++) {
                int n = wc * 32 + jf * 8 + 2 * tig;
                #pragma unroll
                for (int hh = 0; hh < 2; hh++) {
                    int r = rbase + hh * 8;
                    if (r >= M) continue;
                    float v0 = acc[i][jf][hh * 2 + 0] + bs[n];
                    float v1 = acc[i][jf][hh * 2 + 1] + bs[n + 1];
                    *(__half2*)(Ch + (size_t)r * 128 + n) = __floats2half2_rn(v0, v1);
                }
            }
        }
    }
}

// ---------------- fused layer: t1=ssp(aggh@W1+b1); h+=t1@W2+b2; hf=h@Wn+bn ----------------
template <int HASNEXT>
__global__ __launch_bounds__(256) void k_fused(const __half* __restrict__ Ah,
                                               const __half* __restrict__ W1h,
                                               const float* __restrict__ b1,
                                               const __half* __restrict__ W2h,
                                               const float* __restrict__ b2,
                                               float* __restrict__ H,
                                               const __half* __restrict__ Wnh,
                                               const float* __restrict__ bn,
                                               __half* __restrict__ HF, int M) {
    extern __shared__ char dsm[];
    __half* As0 = (__half*)dsm;
    __half* As1 = (__half*)(dsm + 18432);
    __half* Ws  = (__half*)(dsm + 36864);
    float*  bs  = (float*)(dsm + 55296);
    __half* Asc[2] = {As0, As1};
    int tid = threadIdx.x;
    int lane = tid & 31, wid = tid >> 5;
    int wr = wid >> 2, wc = wid & 3;
    int g = lane >> 2, tig = lane & 3;
    int row0 = blockIdx.x * 128;
    if (tid < 128) {
        bs[tid] = b1[tid];
        bs[128 + tid] = b2[tid];
        bs[256 + tid] = HASNEXT ? bn[tid] : 0.0f;
    }
    float acc[4][4][4];
    ZERO_ACC(acc);

    for (int c = 0; c < 2; c++) {
        stage_A_h(Ah, Asc[c], row0, c, M, tid);
        stage_W_h(W1h, Ws, c, tid);
        __syncthreads();
        mma_chunk(Asc[c], Ws, acc, wr, wc, g, tig);
        __syncthreads();
    }
    #pragma unroll
    for (int i = 0; i < 4; i++) {
        #pragma unroll
        for (int jf = 0; jf < 4; jf++) {
            int n = wc * 32 + jf * 8 + 2 * tig;
            #pragma unroll
            for (int hh = 0; hh < 2; hh++) {
                int rloc = wr * 64 + i * 16 + g + hh * 8;
                float v0 = sspf(acc[i][jf][hh * 2 + 0] + bs[n]);
                float v1 = sspf(acc[i][jf][hh * 2 + 1] + bs[n + 1]);
                *(__half2*)&Asc[n >> 6][rloc * 72 + (n & 63)] = __floats2half2_rn(v0, v1);
            }
        }
    }
    ZERO_ACC(acc);
    for (int c = 0; c < 2; c++) {
        stage_W_h(W2h, Ws, c, tid);
        __syncthreads();
        mma_chunk(Asc[c], Ws, acc, wr, wc, g, tig);
        __syncthreads();
    }
    #pragma unroll
    for (int i = 0; i < 4; i++) {
        #pragma unroll
        for (int jf = 0; jf < 4; jf++) {
            int n = wc * 32 + jf * 8 + 2 * tig;
            #pragma unroll
            for (int hh = 0; hh < 2; hh++) {
                int rloc = wr * 64 + i * 16 + g + hh * 8;
                int r = row0 + rloc;
                float v0 = acc[i][jf][hh * 2 + 0] + bs[128 + n];
                float v1 = acc[i][jf][hh * 2 + 1] + bs[128 + n + 1];
                if (r < M) {
                    float2 hold = *(const float2*)(H + (size_t)r * 128 + n);
                    v0 += hold.x; v1 += hold.y;
                    float2 st; st.x = v0; st.y = v1;
                    *(float2*)(H + (size_t)r * 128 + n) = st;
                }
                if (HASNEXT)
                    *(__half2*)&Asc[n >> 6][rloc * 72 + (n & 63)] = __floats2half2_rn(v0, v1);
            }
        }
    }
    if (HASNEXT) {
        ZERO_ACC(acc);
        for (int c = 0; c < 2; c++) {
            stage_W_h(Wnh, Ws, c, tid);
            __syncthreads();
            mma_chunk(Asc[c], Ws, acc, wr, wc, g, tig);
            __syncthreads();
        }
        #pragma unroll
        for (int i = 0; i < 4; i++) {
            #pragma unroll
            for (int jf = 0; jf < 4; jf++) {
                int n = wc * 32 + jf * 8 + 2 * tig;
                #pragma unroll
                for (int hh = 0; hh < 2; hh++) {
                    int r = row0 + wr * 64 + i * 16 + g + hh * 8;
                    if (r >= M) continue;
                    float v0 = acc[i][jf][hh * 2 + 0] + bs[256 + n];
                    float v1 = acc[i][jf][hh * 2 + 1] + bs[256 + n + 1];
                    *(__half2*)(HF + (size_t)r * 128 + n) = __floats2half2_rn(v0, v1);
                }
            }
        }
    }
}

// ---------------- host ----------------
extern "C" void kernel_launch(void* const* d_in, const int* in_sizes, int n_in,
                              void* d_out, int out_size) {
    const int*   r   = (const int*)d_in[0];
    const float* xyz = (const float*)d_in[1];
    const int*   a   = (const int*)d_in[2];
    int base = 3;
    const int* nper = nullptr;
    if (n_in >= 19) { nper = (const int*)d_in[3]; base = 4; }
    const float* embed = (const float*)d_in[base + 0];
    const float* fw1   = (const float*)d_in[base + 1];
    const float* fb1   = (const float*)d_in[base + 2];
    const float* fw2   = (const float*)d_in[base + 3];
    const float* fb2   = (const float*)d_in[base + 4];
    const float* afw   = (const float*)d_in[base + 5];
    const float* afb   = (const float*)d_in[base + 6];
    const float* ow1   = (const float*)d_in[base + 7];
    const float* ob1   = (const float*)d_in[base + 8];
    const float* ow2   = (const float*)d_in[base + 9];
    const float* ob2   = (const float*)d_in[base + 10];
    const float* aw1   = (const float*)d_in[base + 11];
    const float* ab1   = (const float*)d_in[base + 12];
    const float* aw2   = (const float*)d_in[base + 13];
    const float* ab2   = (const float*)d_in[base + 14];
    float* out = (float*)d_out;

    float *ph, *pts, *pb1pad;
    __half *phf, *paggh, *ptbl, *pwhT;
    cudaGetSymbolAddress((void**)&ph,     g_h);
    cudaGetSymbolAddress((void**)&phf,    g_hf);
    cudaGetSymbolAddress((void**)&paggh,  g_aggh);
    cudaGetSymbolAddress((void**)&pts,    g_ts);
    cudaGetSymbolAddress((void**)&ptbl,   g_table);
    cudaGetSymbolAddress((void**)&pwhT,   g_whT);
    cudaGetSymbolAddress((void**)&pb1pad, g_b1pad);

    const int FUSED_SMEM = 56832;
    cudaFuncSetAttribute(k_fused<1>, cudaFuncAttributeMaxDynamicSharedMemorySize, FUSED_SMEM);
    cudaFuncSetAttribute(k_fused<0>, cudaFuncAttributeMaxDynamicSharedMemorySize, FUSED_SMEM);

    k_init<<<(N_ATOMS * 32 + 255) / 256, 256>>>(r, embed, out, out_size);
    k_edges<<<(N_EDGES + 255) / 256, 256>>>(a, xyz);
    k_scan<<<1, 1024>>>();
    k_scatter<<<(N_EDGES + 255) / 256, 256>>>(a);
    k_prep<<<dim3(4, 4, 12), dim3(32, 8)>>>(ow1, ow2, afw, fw2);
    k_pad<<<64, 256>>>(aw1, ab1, aw2);
    k_ts<<<3 * (TBL / 16), 256>>>(fw1, fb1);
    for (int L = 0; L < 3; L++)
        k_gemm<1, 0><<<TBL / 128, 256>>>(pts + (size_t)L * TBL * 128,
                                         pwhT + (size_t)(9 + L) * 16384, fb2 + L * 128,
                                         ptbl + (size_t)L * TBL * 128,
                                         nullptr, nullptr, nullptr, TBL);

    int gemm_grid = (N_ATOMS + 127) / 128;
    // initial hf = h @ afw0 + afb0
    k_gemm<1, 0><<<gemm_grid, 256>>>(ph, pwhT + (size_t)6 * 16384, afb,
                                     phf, nullptr, nullptr, nullptr, N_ATOMS);
    for (int L = 0; L < 3; L++) {
        k_agg<<<N_ATOMS / 8, dim3(32, 8)>>>(ptbl + (size_t)L * TBL * 128);
        if (L < 2)
            k_fused<1><<<gemm_grid, 256, FUSED_SMEM>>>(
                paggh, pwhT + (size_t)L * 16384, ob1 + L * 128,
                pwhT + (size_t)(3 + L) * 16384, ob2 + L * 128, ph,
                pwhT + (size_t)(6 + L + 1) * 16384, afb + (L + 1) * 128, phf, N_ATOMS);
        else
            k_fused<0><<<gemm_grid, 256, FUSED_SMEM>>>(
                paggh, pwhT + (size_t)L * 16384, ob1 + L * 128,
                pwhT + (size_t)(3 + L) * 16384, ob2 + L * 128, ph,
                nullptr, nullptr, nullptr, N_ATOMS);
    }
    // fused readout: y = ssp(h @ w1pad + b1pad) . aw2pad + ab2, block-summed into out
    k_gemm<0, 1><<<gemm_grid, 256>>>(ph, pwhT + (size_t)12 * 16384, pb1pad,
                                     nullptr, ab2, out, nper, N_ATOMS);
}

// round 9
// speedup vs baseline: 2.2581x; 1.1122x over previous
#include <cuda_runtime.h>
#include <cuda_fp16.h>
#include <math.h>

#define N_ATOMS 50000
#define N_EDGES 800000
#define TBL 16384
#define DMAXF 14.0f
#define LN2F 0.6931471805599453f

// ---------------- device scratch ----------------
__device__ float    g_h   [N_ATOMS * 128];
__device__ __half   g_hf  [N_ATOMS * 128];
__device__ __half   g_aggh[N_ATOMS * 128];
__device__ float    g_d   [N_EDGES];
__device__ unsigned g_metap[N_EDGES];        // src (17b) | table-index (14b) << 17
__device__ int      g_counts[N_ATOMS];
__device__ int      g_start [N_ATOMS];
__device__ int      g_cursor[N_ATOMS];
__device__ __half   g_table[3 * TBL * 128];
__device__ __half   g_whT  [13 * 128 * 128]; // [n][k]: 0-2 ow1, 3-5 ow2, 6-8 afw, 9-11 fw2, 12 w1pad
__device__ __half   g_w1T  [3 * 128 * 32];   // fw1 transposed [n=128][k=32]
__device__ __half   g_embedF[128 * 128];     // embed @ afw0 + afb0 (100 rows used)
__device__ float    g_b1pad[128];
__device__ float    g_aw2pad[128];

__device__ __forceinline__ float sspf(float x) {
    return fmaxf(x, 0.0f) + log1pf(expf(-fabsf(x))) - LN2F;
}

__device__ __forceinline__ void mma_f16(float* d, const unsigned* a, const unsigned* b) {
    asm volatile(
        "mma.sync.aligned.m16n8k16.row.col.f32.f16.f16.f32 "
        "{%0,%1,%2,%3}, {%4,%5,%6,%7}, {%8,%9}, {%0,%1,%2,%3};\n"
        : "+f"(d[0]), "+f"(d[1]), "+f"(d[2]), "+f"(d[3])
        : "r"(a[0]), "r"(a[1]), "r"(a[2]), "r"(a[3]), "r"(b[0]), "r"(b[1]));
}

// ---------------- init ----------------
__global__ void k_init(const int* __restrict__ r, const float* __restrict__ embed,
                       float* __restrict__ out, int out_size) {
    int idx = blockIdx.x * blockDim.x + threadIdx.x;
    if (idx < N_ATOMS * 32) {
        int atom = idx >> 5, j = idx & 31;
        ((float4*)g_h)[atom * 32 + j] = ((const float4*)embed)[(size_t)r[atom] * 32 + j];
    }
    if (idx < N_ATOMS) g_counts[idx] = 0;
    if (idx < out_size) out[idx] = 0.0f;
}

// ---------------- edges ----------------
__global__ void k_edges(const int* __restrict__ a, const float* __restrict__ xyz) {
    int e = blockIdx.x * blockDim.x + threadIdx.x;
    if (e >= N_EDGES) return;
    int d0 = a[2 * e], s0 = a[2 * e + 1];
    float dx = xyz[3 * d0 + 0] - xyz[3 * s0 + 0];
    float dy = xyz[3 * d0 + 1] - xyz[3 * s0 + 1];
    float dz = xyz[3 * d0 + 2] - xyz[3 * s0 + 2];
    g_d[e] = sqrtf(dx * dx + dy * dy + dz * dz + 1e-12f);
    atomicAdd(&g_counts[d0], 1);
}

// ---------------- exclusive scan ----------------
__global__ __launch_bounds__(1024) void k_scan() {
    __shared__ int wsum[32];
    __shared__ int carry;
    __shared__ int tot;
    int t = threadIdx.x, lane = t & 31, w = t >> 5;
    if (t == 0) carry = 0;
    __syncthreads();
    for (int base = 0; base < N_ATOMS; base += 1024) {
        int i = base + t;
        int v = (i < N_ATOMS) ? g_counts[i] : 0;
        int incl = v;
        #pragma unroll
        for (int off = 1; off < 32; off <<= 1) {
            int x = __shfl_up_sync(0xffffffffu, incl, off);
            if (lane >= off) incl += x;
        }
        if (lane == 31) wsum[w] = incl;
        __syncthreads();
        if (w == 0) {
            int s = wsum[lane];
            int si = s;
            #pragma unroll
            for (int off = 1; off < 32; off <<= 1) {
                int x = __shfl_up_sync(0xffffffffu, si, off);
                if (lane >= off) si += x;
            }
            wsum[lane] = si - s;
            if (lane == 31) tot = si;
        }
        __syncthreads();
        int excl = carry + wsum[w] + incl - v;
        if (i < N_ATOMS) { g_start[i] = excl; g_cursor[i] = excl; }
        __syncthreads();
        if (t == 0) carry += tot;
        __syncthreads();
    }
}

// ---------------- scatter: pack (src | i0<<17) ----------------
__global__ void k_scatter(const int* __restrict__ a) {
    int e = blockIdx.x * blockDim.x + threadIdx.x;
    if (e >= N_EDGES) return;
    int d0 = a[2 * e];
    int pos = atomicAdd(&g_cursor[d0], 1);
    float d = g_d[e];
    float u = d * ((float)(TBL - 1) / DMAXF);
    int i0 = (int)(u + 0.5f);
    i0 = min(i0, TBL - 1);
    g_metap[pos] = (unsigned)a[2 * e + 1] | ((unsigned)i0 << 17);
}

// ---------------- weight transpose+convert: fp32 [k][n] -> half [n][k] ----------------
__global__ void k_prep(const float* __restrict__ ow1, const float* __restrict__ ow2,
                       const float* __restrict__ afw, const float* __restrict__ fw2) {
    __shared__ float t[32][33];
    int mat = blockIdx.z;
    const float* src = (mat < 3) ? ow1 + (size_t)mat * 16384
                     : (mat < 6) ? ow2 + (size_t)(mat - 3) * 16384
                     : (mat < 9) ? afw + (size_t)(mat - 6) * 16384
                                 : fw2 + (size_t)(mat - 9) * 16384;
    __half* dst = g_whT + (size_t)mat * 16384;
    int k0 = blockIdx.y * 32, n0 = blockIdx.x * 32;
    int tx = threadIdx.x, ty = threadIdx.y;   // (32, 8)
    #pragma unroll
    for (int q = 0; q < 4; q++)
        t[ty + q * 8][tx] = src[(size_t)(k0 + ty + q * 8) * 128 + n0 + tx];
    __syncthreads();
    #pragma unroll
    for (int q = 0; q < 4; q++)
        dst[(size_t)(n0 + ty + q * 8) * 128 + k0 + tx] = __float2half_rn(t[tx][ty + q * 8]);
}

// ---------------- fw1 transpose: [L][32][128] fp32 -> [L][128][32] half ----------------
__global__ void k_prep1(const float* __restrict__ fw1) {
    int i = blockIdx.x * 256 + threadIdx.x;
    if (i >= 3 * 128 * 32) return;
    int L = i >> 12, rest = i & 4095, n = rest >> 5, k = rest & 31;
    g_w1T[i] = __float2half_rn(fw1[L * 4096 + k * 128 + n]);
}

// ---------------- readout weight pad ----------------
__global__ void k_pad(const float* __restrict__ aw1, const float* __restrict__ ab1,
                      const float* __restrict__ aw2) {
    int i = blockIdx.x * 256 + threadIdx.x;
    if (i < 128 * 128) {
        int n = i >> 7, k = i & 127;
        g_whT[12 * 16384 + i] = __float2half_rn((n < 64) ? aw1[k * 64 + n] : 0.0f);
    }
    if (i < 128) {
        g_b1pad[i]  = (i < 64) ? ab1[i] : 0.0f;
        g_aw2pad[i] = (i < 64) ? aw2[i] : 0.0f;
    }
}

// ---------------- gather hf0 = embedF[r] ----------------
__global__ void k_hf0(const int* __restrict__ r) {
    int idx = blockIdx.x * 256 + threadIdx.x;
    if (idx >= N_ATOMS * 16) return;
    int atom = idx >> 4, q = idx & 15;
    ((uint4*)g_hf)[idx] = ((const uint4*)g_embedF)[(size_t)r[atom] * 16 + q];
}

// ================= GEMM building blocks =================
__device__ __forceinline__ void stage_A_f(const float* __restrict__ A, __half* As,
                                          int row0, int c, int M, int tid) {
    int ar = tid >> 1;
    int k0 = (tid & 1) * 32;
    const float* ap = A + (size_t)(row0 + ar) * 128 + c * 64 + k0;
    bool valid = (row0 + ar) < M;
    #pragma unroll
    for (int p = 0; p < 8; p++) {
        float4 v = make_float4(0.f, 0.f, 0.f, 0.f);
        if (valid) v = *(const float4*)(ap + p * 4);
        *(__half2*)&As[ar * 72 + k0 + p * 4]     = __floats2half2_rn(v.x, v.y);
        *(__half2*)&As[ar * 72 + k0 + p * 4 + 2] = __floats2half2_rn(v.z, v.w);
    }
}

__device__ __forceinline__ void stage_A_h(const __half* __restrict__ Ah, __half* As,
                                          int row0, int c, int M, int tid) {
    #pragma unroll
    for (int p = 0; p < 4; p++) {
        int idx = tid + p * 256;
        int m = idx >> 3, k8 = (idx & 7) * 8;
        uint4 v = make_uint4(0, 0, 0, 0);
        if (row0 + m < M) v = *(const uint4*)(Ah + (size_t)(row0 + m) * 128 + c * 64 + k8);
        *(uint4*)&As[m * 72 + k8] = v;
    }
}

__device__ __forceinline__ void stage_W_h(const __half* __restrict__ Wh, __half* Ws,
                                          int c, int tid) {
    #pragma unroll
    for (int p = 0; p < 4; p++) {
        int idx = tid + p * 256;
        int n = idx >> 3, k8 = (idx & 7) * 8;
        *(uint4*)&Ws[n * 72 + k8] = *(const uint4*)(Wh + (size_t)n * 128 + c * 64 + k8);
    }
}

__device__ __forceinline__ void mma_chunk(const __half* As, const __half* Ws,
                                          float acc[4][4][4], int wr, int wc, int g, int tig) {
    #pragma unroll
    for (int ks = 0; ks < 64; ks += 16) {
        unsigned af[4][4], bf[4][2];
        #pragma unroll
        for (int i = 0; i < 4; i++) {
            int r = wr * 64 + i * 16 + g;
            af[i][0] = *(const unsigned*)&As[r * 72 + ks + tig * 2];
            af[i][1] = *(const unsigned*)&As[(r + 8) * 72 + ks + tig * 2];
            af[i][2] = *(const unsigned*)&As[r * 72 + ks + tig * 2 + 8];
            af[i][3] = *(const unsigned*)&As[(r + 8) * 72 + ks + tig * 2 + 8];
        }
        #pragma unroll
        for (int jf = 0; jf < 4; jf++) {
            int n = wc * 32 + jf * 8 + g;
            bf[jf][0] = *(const unsigned*)&Ws[n * 72 + ks + tig * 2];
            bf[jf][1] = *(const unsigned*)&Ws[n * 72 + ks + tig * 2 + 8];
        }
        #pragma unroll
        for (int i = 0; i < 4; i++)
            #pragma unroll
            for (int jf = 0; jf < 4; jf++)
                mma_f16(acc[i][jf], af[i], bf[jf]);
    }
}

#define ZERO_ACC(acc) { _Pragma("unroll") for (int i = 0; i < 4; i++) _Pragma("unroll") \
    for (int jf = 0; jf < 4; jf++) _Pragma("unroll") for (int q = 0; q < 4; q++) acc[i][jf][q] = 0.0f; }

// ---------------- fused table build (dynamic smem; Ts stride 136 holds full 128 cols) ----------------
// layout: Gs[128*40] | Ts[128*136] | Ws[128*72] | bs1[128] | bs2[128]  = 64512 B
#define TBL_SMEM (128 * 40 * 2 + 128 * 136 * 2 + 128 * 72 * 2 + 512 + 512)
__global__ __launch_bounds__(256) void k_tbl(const float* __restrict__ fb1,
                                             const float* __restrict__ fb2) {
    extern __shared__ char dsm[];
    __half* Gs = (__half*)dsm;                          // [m][k=32] stride 40
    __half* Ts = (__half*)(dsm + 10240);                // [m][k=128] stride 136
    __half* Ws = (__half*)(dsm + 10240 + 34816);        // [n][k] stride 72 (or 40 in GEMM1)
    float* bs1 = (float*)(dsm + 10240 + 34816 + 18432);
    float* bs2 = (float*)(dsm + 10240 + 34816 + 18432 + 512);
    int tid = threadIdx.x;
    int lane = tid & 31, wid = tid >> 5;
    int wr = wid >> 2, wc = wid & 3;
    int g = lane >> 2, tig = lane & 3;
    int L = blockIdx.x / (TBL / 128);
    int e0 = (blockIdx.x % (TBL / 128)) * 128;
    float width = 5.0f / 31.0f;
    float coeff = -0.5f / (width * width);
    for (int i = tid; i < 128 * 32; i += 256) {
        int m = i >> 5, k = i & 31;
        float d = (float)(e0 + m) * (DMAXF / (float)(TBL - 1));
        float x = d - (float)k * width;
        Gs[m * 40 + k] = __float2half_rn(expf(coeff * x * x));
    }
    if (tid < 128) { bs1[tid] = fb1[L * 128 + tid]; bs2[tid] = fb2[L * 128 + tid]; }
    // stage w1T [n=128][k=32] into Ws stride 40
    for (int i = tid; i < 128 * 4; i += 256) {
        int n = i >> 2, k8 = (i & 3) * 8;
        *(uint4*)&Ws[n * 40 + k8] = *(const uint4*)&g_w1T[(size_t)(L * 128 + n) * 32 + k8];
    }
    __syncthreads();
    // GEMM1: K=32
    float acc[4][4][4];
    ZERO_ACC(acc);
    #pragma unroll
    for (int ks = 0; ks < 32; ks += 16) {
        unsigned af[4][4], bf[4][2];
        #pragma unroll
        for (int i = 0; i < 4; i++) {
            int r = wr * 64 + i * 16 + g;
            af[i][0] = *(const unsigned*)&Gs[r * 40 + ks + tig * 2];
            af[i][1] = *(const unsigned*)&Gs[(r + 8) * 40 + ks + tig * 2];
            af[i][2] = *(const unsigned*)&Gs[r * 40 + ks + tig * 2 + 8];
            af[i][3] = *(const unsigned*)&Gs[(r + 8) * 40 + ks + tig * 2 + 8];
        }
        #pragma unroll
        for (int jf = 0; jf < 4; jf++) {
            int n = wc * 32 + jf * 8 + g;
            bf[jf][0] = *(const unsigned*)&Ws[n * 40 + ks + tig * 2];
            bf[jf][1] = *(const unsigned*)&Ws[n * 40 + ks + tig * 2 + 8];
        }
        #pragma unroll
        for (int i = 0; i < 4; i++)
            #pragma unroll
            for (int jf = 0; jf < 4; jf++)
                mma_f16(acc[i][jf], af[i], bf[jf]);
    }
    // epilogue1: ts = ssp(acc + b1) -> Ts (full 128-col rows, stride 136)
    #pragma unroll
    for (int i = 0; i < 4; i++) {
        #pragma unroll
        for (int jf = 0; jf < 4; jf++) {
            int n = wc * 32 + jf * 8 + 2 * tig;
            #pragma unroll
            for (int hh = 0; hh < 2; hh++) {
                int rloc = wr * 64 + i * 16 + g + hh * 8;
                float v0 = sspf(acc[i][jf][hh * 2 + 0] + bs1[n]);
                float v1 = sspf(acc[i][jf][hh * 2 + 1] + bs1[n + 1]);
                *(__half2*)&Ts[rloc * 136 + n] = __floats2half2_rn(v0, v1);
            }
        }
    }
    ZERO_ACC(acc);
    // GEMM2: K=128 over fw2T
    const __half* w2T = g_whT + (size_t)(9 + L) * 16384;
    for (int c = 0; c < 2; c++) {
        __syncthreads();
        stage_W_h(w2T, Ws, c, tid);
        __syncthreads();
        #pragma unroll
        for (int ks = 0; ks < 64; ks += 16) {
            unsigned af[4][4], bf[4][2];
            #pragma unroll
            for (int i = 0; i < 4; i++) {
                int r = wr * 64 + i * 16 + g;
                af[i][0] = *(const unsigned*)&Ts[r * 136 + c * 64 + ks + tig * 2];
                af[i][1] = *(const unsigned*)&Ts[(r + 8) * 136 + c * 64 + ks + tig * 2];
                af[i][2] = *(const unsigned*)&Ts[r * 136 + c * 64 + ks + tig * 2 + 8];
                af[i][3] = *(const unsigned*)&Ts[(r + 8) * 136 + c * 64 + ks + tig * 2 + 8];
            }
            #pragma unroll
            for (int jf = 0; jf < 4; jf++) {
                int n = wc * 32 + jf * 8 + g;
                bf[jf][0] = *(const unsigned*)&Ws[n * 72 + ks + tig * 2];
                bf[jf][1] = *(const unsigned*)&Ws[n * 72 + ks + tig * 2 + 8];
            }
            #pragma unroll
            for (int i = 0; i < 4; i++)
                #pragma unroll
                for (int jf = 0; jf < 4; jf++)
                    mma_f16(acc[i][jf], af[i], bf[jf]);
        }
    }
    // epilogue2 -> g_table
    __half* trow = g_table + ((size_t)L * TBL + e0) * 128;
    #pragma unroll
    for (int i = 0; i < 4; i++) {
        #pragma unroll
        for (int jf = 0; jf < 4; jf++) {
            int n = wc * 32 + jf * 8 + 2 * tig;
            #pragma unroll
            for (int hh = 0; hh < 2; hh++) {
                int rloc = wr * 64 + i * 16 + g + hh * 8;
                float v0 = acc[i][jf][hh * 2 + 0] + bs2[n];
                float v1 = acc[i][jf][hh * 2 + 1] + bs2[n + 1];
                *(__half2*)&trow[(size_t)rloc * 128 + n] = __floats2half2_rn(v0, v1);
            }
        }
    }
}

// ---------------- aggregation: 2 edges/iter, 16B lanes, warp per atom ----------------
__global__ __launch_bounds__(256) void k_agg(const __half* __restrict__ tbl) {
    int atom = blockIdx.x * 8 + threadIdx.y;
    int lane = threadIdx.x;
    int hid = lane >> 4;               // 0: even edges, 1: odd edges
    int fl = lane & 15;                // features 8*fl .. 8*fl+7
    int s = g_start[atom], c = g_counts[atom];
    float acc[8];
    #pragma unroll
    for (int q = 0; q < 8; q++) acc[q] = 0.0f;
    const uint4* t4 = (const uint4*)tbl;
    const uint4* h4 = (const uint4*)g_hf;
    #pragma unroll 2
    for (int e = hid; e < c; e += 2) {
        unsigned m = __ldg(&g_metap[s + e]);
        int src = m & 0x1FFFF;
        int i0 = m >> 17;
        uint4 wv = __ldg(&t4[(size_t)i0 * 16 + fl]);
        uint4 hv = __ldg(&h4[(size_t)src * 16 + fl]);
        const __half2* wp = (const __half2*)&wv;
        const __half2* hp = (const __half2*)&hv;
        #pragma unroll
        for (int q = 0; q < 4; q++) {
            float2 wf = __half22float2(wp[q]);
            float2 hf = __half22float2(hp[q]);
            acc[2 * q]     = fmaf(hf.x, wf.x, acc[2 * q]);
            acc[2 * q + 1] = fmaf(hf.y, wf.y, acc[2 * q + 1]);
        }
    }
    #pragma unroll
    for (int q = 0; q < 8; q++) acc[q] += __shfl_down_sync(0xffffffffu, acc[q], 16);
    if (hid == 0) {
        uint4 st;
        __half2* sp = (__half2*)&st;
        #pragma unroll
        for (int q = 0; q < 4; q++) sp[q] = __floats2half2_rn(acc[2 * q], acc[2 * q + 1]);
        ((uint4*)g_aggh)[(size_t)atom * 16 + fl] = st;
    }
}

// ---------------- generic GEMM: fp32-A, half-W; OUTH -> half out; RED -> fused readout ----------------
template <int OUTH, int RED>
__global__ __launch_bounds__(256) void k_gemm(const float* __restrict__ A,
                                              const __half* __restrict__ Wh,
                                              const float* __restrict__ bias,
                                              __half* __restrict__ Ch,
                                              const float* __restrict__ ab2,
                                              float* __restrict__ out,
                                              const int* __restrict__ nper, int M) {
    __shared__ __half As[128 * 72];
    __shared__ __half Ws[128 * 72];
    __shared__ float bs[128];
    __shared__ float aw2s[128];
    __shared__ float srow[128];
    int tid = threadIdx.x;
    int lane = tid & 31, wid = tid >> 5;
    int wr = wid >> 2, wc = wid & 3;
    int g = lane >> 2, tig = lane & 3;
    int row0 = blockIdx.x * 128;
    float acc[4][4][4];
    ZERO_ACC(acc);
    if (tid < 128) {
        bs[tid] = bias[tid];
        if (RED) { aw2s[tid] = g_aw2pad[tid]; srow[tid] = 0.0f; }
    }

    for (int c = 0; c < 2; c++) {
        stage_A_f(A, As, row0, c, M, tid);
        stage_W_h(Wh, Ws, c, tid);
        __syncthreads();
        mma_chunk(As, Ws, acc, wr, wc, g, tig);
        __syncthreads();
    }

    if (RED) {
        int np = nper ? __ldg(nper) : 5000;
        float ab2v = __ldg(ab2);
        #pragma unroll
        for (int i = 0; i < 4; i++) {
            #pragma unroll
            for (int hh = 0; hh < 2; hh++) {
                int rloc = wr * 64 + i * 16 + g + hh * 8;
                float s = 0.0f;
                #pragma unroll
                for (int jf = 0; jf < 4; jf++) {
                    int n = wc * 32 + jf * 8 + 2 * tig;
                    float v0 = sspf(acc[i][jf][hh * 2 + 0] + bs[n]);
                    float v1 = sspf(acc[i][jf][hh * 2 + 1] + bs[n + 1]);
                    s += v0 * aw2s[n] + v1 * aw2s[n + 1];
                }
                atomicAdd(&srow[rloc], s);
            }
        }
        __syncthreads();
        if (tid < 128) {
            int r = row0 + tid;
            if (r < M) atomicAdd(&out[r / np], srow[tid] + ab2v);
        }
    } else {
        #pragma unroll
        for (int i = 0; i < 4; i++) {
            int rbase = row0 + wr * 64 + i * 16 + g;
            #pragma unroll
            for (int jf = 0; jf < 4; jf++) {
                int n = wc * 32 + jf * 8 + 2 * tig;
                #pragma unroll
                for (int hh = 0; hh < 2; hh++) {
                    int r = rbase + hh * 8;
                    if (r >= M) continue;
                    float v0 = acc[i][jf][hh * 2 + 0] + bs[n];
                    float v1 = acc[i][jf][hh * 2 + 1] + bs[n + 1];
                    *(__half2*)(Ch + (size_t)r * 128 + n) = __floats2half2_rn(v0, v1);
                }
            }
        }
    }
}

// ---------------- fused layer: t1=ssp(aggh@W1+b1); h+=t1@W2+b2; hf=h@Wn+bn ----------------
template <int HASNEXT>
__global__ __launch_bounds__(256) void k_fused(const __half* __restrict__ Ah,
                                               const __half* __restrict__ W1h,
                                               const float* __restrict__ b1,
                                               const __half* __restrict__ W2h,
                                               const float* __restrict__ b2,
                                               float* __restrict__ H,
                                               const __half* __restrict__ Wnh,
                                               const float* __restrict__ bn,
                                               __half* __restrict__ HF, int M) {
    extern __shared__ char dsm[];
    __half* As0 = (__half*)dsm;
    __half* As1 = (__half*)(dsm + 18432);
    __half* Ws  = (__half*)(dsm + 36864);
    float*  bs  = (float*)(dsm + 55296);
    __half* Asc[2] = {As0, As1};
    int tid = threadIdx.x;
    int lane = tid & 31, wid = tid >> 5;
    int wr = wid >> 2, wc = wid & 3;
    int g = lane >> 2, tig = lane & 3;
    int row0 = blockIdx.x * 128;
    if (tid < 128) {
        bs[tid] = b1[tid];
        bs[128 + tid] = b2[tid];
        bs[256 + tid] = HASNEXT ? bn[tid] : 0.0f;
    }
    float acc[4][4][4];
    ZERO_ACC(acc);

    for (int c = 0; c < 2; c++) {
        stage_A_h(Ah, Asc[c], row0, c, M, tid);
        stage_W_h(W1h, Ws, c, tid);
        __syncthreads();
        mma_chunk(Asc[c], Ws, acc, wr, wc, g, tig);
        __syncthreads();
    }
    #pragma unroll
    for (int i = 0; i < 4; i++) {
        #pragma unroll
        for (int jf = 0; jf < 4; jf++) {
            int n = wc * 32 + jf * 8 + 2 * tig;
            #pragma unroll
            for (int hh = 0; hh < 2; hh++) {
                int rloc = wr * 64 + i * 16 + g + hh * 8;
                float v0 = sspf(acc[i][jf][hh * 2 + 0] + bs[n]);
                float v1 = sspf(acc[i][jf][hh * 2 + 1] + bs[n + 1]);
                *(__half2*)&Asc[n >> 6][rloc * 72 + (n & 63)] = __floats2half2_rn(v0, v1);
            }
        }
    }
    ZERO_ACC(acc);
    for (int c = 0; c < 2; c++) {
        stage_W_h(W2h, Ws, c, tid);
        __syncthreads();
        mma_chunk(Asc[c], Ws, acc, wr, wc, g, tig);
        __syncthreads();
    }
    #pragma unroll
    for (int i = 0; i < 4; i++) {
        #pragma unroll
        for (int jf = 0; jf < 4; jf++) {
            int n = wc * 32 + jf * 8 + 2 * tig;
            #pragma unroll
            for (int hh = 0; hh < 2; hh++) {
                int rloc = wr * 64 + i * 16 + g + hh * 8;
                int r = row0 + rloc;
                float v0 = acc[i][jf][hh * 2 + 0] + bs[128 + n];
                float v1 = acc[i][jf][hh * 2 + 1] + bs[128 + n + 1];
                if (r < M) {
                    float2 hold = *(const float2*)(H + (size_t)r * 128 + n);
                    v0 += hold.x; v1 += hold.y;
                    float2 st; st.x = v0; st.y = v1;
                    *(float2*)(H + (size_t)r * 128 + n) = st;
                }
                if (HASNEXT)
                    *(__half2*)&Asc[n >> 6][rloc * 72 + (n & 63)] = __floats2half2_rn(v0, v1);
            }
        }
    }
    if (HASNEXT) {
        ZERO_ACC(acc);
        for (int c = 0; c < 2; c++) {
            stage_W_h(Wnh, Ws, c, tid);
            __syncthreads();
            mma_chunk(Asc[c], Ws, acc, wr, wc, g, tig);
            __syncthreads();
        }
        #pragma unroll
        for (int i = 0; i < 4; i++) {
            #pragma unroll
            for (int jf = 0; jf < 4; jf++) {
                int n = wc * 32 + jf * 8 + 2 * tig;
                #pragma unroll
                for (int hh = 0; hh < 2; hh++) {
                    int r = row0 + wr * 64 + i * 16 + g + hh * 8;
                    if (r >= M) continue;
                    float v0 = acc[i][jf][hh * 2 + 0] + bs[256 + n];
                    float v1 = acc[i][jf][hh * 2 + 1] + bs[256 + n + 1];
                    *(__half2*)(HF + (size_t)r * 128 + n) = __floats2half2_rn(v0, v1);
                }
            }
        }
    }
}

// ---------------- host ----------------
extern "C" void kernel_launch(void* const* d_in, const int* in_sizes, int n_in,
                              void* d_out, int out_size) {
    const int*   r   = (const int*)d_in[0];
    const float* xyz = (const float*)d_in[1];
    const int*   a   = (const int*)d_in[2];
    int base = 3;
    const int* nper = nullptr;
    if (n_in >= 19) { nper = (const int*)d_in[3]; base = 4; }
    const float* embed = (const float*)d_in[base + 0];
    const float* fw1   = (const float*)d_in[base + 1];
    const float* fb1   = (const float*)d_in[base + 2];
    const float* fw2   = (const float*)d_in[base + 3];
    const float* fb2   = (const float*)d_in[base + 4];
    const float* afw   = (const float*)d_in[base + 5];
    const float* afb   = (const float*)d_in[base + 6];
    const float* ow1   = (const float*)d_in[base + 7];
    const float* ob1   = (const float*)d_in[base + 8];
    const float* ow2   = (const float*)d_in[base + 9];
    const float* ob2   = (const float*)d_in[base + 10];
    const float* aw1   = (const float*)d_in[base + 11];
    const float* ab1   = (const float*)d_in[base + 12];
    const float* aw2   = (const float*)d_in[base + 13];
    const float* ab2   = (const float*)d_in[base + 14];
    float* out = (float*)d_out;

    float *ph, *pb1pad;
    __half *phf, *paggh, *ptbl, *pwhT, *pembedF;
    cudaGetSymbolAddress((void**)&ph,      g_h);
    cudaGetSymbolAddress((void**)&phf,     g_hf);
    cudaGetSymbolAddress((void**)&paggh,   g_aggh);
    cudaGetSymbolAddress((void**)&ptbl,    g_table);
    cudaGetSymbolAddress((void**)&pwhT,    g_whT);
    cudaGetSymbolAddress((void**)&pembedF, g_embedF);
    cudaGetSymbolAddress((void**)&pb1pad,  g_b1pad);

    const int FUSED_SMEM = 56832;
    cudaFuncSetAttribute(k_fused<1>, cudaFuncAttributeMaxDynamicSharedMemorySize, FUSED_SMEM);
    cudaFuncSetAttribute(k_fused<0>, cudaFuncAttributeMaxDynamicSharedMemorySize, FUSED_SMEM);
    cudaFuncSetAttribute(k_tbl, cudaFuncAttributeMaxDynamicSharedMemorySize, TBL_SMEM);

    k_init<<<(N_ATOMS * 32 + 255) / 256, 256>>>(r, embed, out, out_size);
    k_edges<<<(N_EDGES + 255) / 256, 256>>>(a, xyz);
    k_scan<<<1, 1024>>>();
    k_scatter<<<(N_EDGES + 255) / 256, 256>>>(a);
    k_prep<<<dim3(4, 4, 12), dim3(32, 8)>>>(ow1, ow2, afw, fw2);
    k_prep1<<<48, 256>>>(fw1);
    k_pad<<<64, 256>>>(aw1, ab1, aw2);
    k_tbl<<<3 * (TBL / 128), 256, TBL_SMEM>>>(fb1, fb2);

    // embedF = embed @ afw0 + afb0 (100 rows, one block), then hf0 = embedF[r]
    k_gemm<1, 0><<<1, 256>>>(embed, pwhT + (size_t)6 * 16384, afb,
                             pembedF, nullptr, nullptr, nullptr, 100);
    k_hf0<<<(N_ATOMS * 16 + 255) / 256, 256>>>(r);

    int gemm_grid = (N_ATOMS + 127) / 128;
    for (int L = 0; L < 3; L++) {
        k_agg<<<N_ATOMS / 8, dim3(32, 8)>>>(ptbl + (size_t)L * TBL * 128);
        if (L < 2)
            k_fused<1><<<gemm_grid, 256, FUSED_SMEM>>>(
                paggh, pwhT + (size_t)L * 16384, ob1 + L * 128,
                pwhT + (size_t)(3 + L) * 16384, ob2 + L * 128, ph,
                pwhT + (size_t)(6 + L + 1) * 16384, afb + (L + 1) * 128, phf, N_ATOMS);
        else
            k_fused<0><<<gemm_grid, 256, FUSED_SMEM>>>(
                paggh, pwhT + (size_t)L * 16384, ob1 + L * 128,
                pwhT + (size_t)(3 + L) * 16384, ob2 + L * 128, ph,
                nullptr, nullptr, nullptr, N_ATOMS);
    }
    // fused readout
    k_gemm<0, 1><<<gemm_grid, 256>>>(ph, pwhT + (size_t)12 * 16384, pb1pad,
                                     nullptr, ab2, out, nper, N_ATOMS);
}